// round 7
// baseline (speedup 1.0000x reference)
#include <cuda_runtime.h>
#include <math.h>

#define BB 128
#define NN 4096
#define DD 64
#define SS 7
#define HH 128
#define NUM_ITERS 3
#define EPSV 1e-8f
#define LN_EPS 1e-5f
#define SCALE 0.125f   // 64^-0.5

typedef unsigned long long u64;

// persistent scratch (no allocation allowed)
__device__ float g_slots[BB*SS*DD];
__device__ float g_qt[BB*SS*DD];    // qw = ln_in_w ⊙ (q@Wk)  [b][s][64]
__device__ float g_qsc[BB*SS*2];    // {sw, sb} per (b,s)
__device__ float g_u[BB*SS*DD];     // G1 = sum_n (p*r) * x
__device__ float g_den[BB*SS];      // sum_n p
__device__ float g_c2[BB*SS];       // sum_n p*r*m
__device__ float g_M[DD*DD];        // scale * Wq^T @ Wk      [e][t]
__device__ float g_CT[DD*3*DD];     // (W_ih @ Wv)^T          [e][j]
__device__ float g_WHHT[DD*3*DD];   // W_hh^T                 [e][j]
__device__ float g_W1T[DD*HH];      // W1^T                   [e][j]
__device__ float g_W2T[HH*DD];      // W2^T                   [j][d]
__device__ int   g_cnt[BB];         // per-batch tile completion counter

// ---------------------------------------------------------------------------
__device__ __forceinline__ u64 pk(float lo, float hi){
    u64 r; asm("mov.b64 %0,{%1,%2};" : "=l"(r) : "f"(lo), "f"(hi)); return r;
}
__device__ __forceinline__ void upk(u64 v, float& lo, float& hi){
    asm("mov.b64 {%0,%1},%2;" : "=f"(lo), "=f"(hi) : "l"(v));
}
__device__ __forceinline__ void fma2(u64& d, u64 a, u64 b){
    asm("fma.rn.f32x2 %0,%1,%2,%0;" : "+l"(d) : "l"(a), "l"(b));
}
__device__ __forceinline__ void add2(u64& d, u64 a){
    asm("add.rn.f32x2 %0,%1,%0;" : "+l"(d) : "l"(a));
}
// fast exp: exp2 split with magic bias + degree-6 poly (rel err ~1e-7)
__device__ __forceinline__ float fexp(float x){
    float t = fmaxf(x * 1.4426950408889634f, -126.f);
    float z = __fadd_rn(t, 12582912.f);
    int n = __float_as_int(z) - 0x4B400000;
    float f = t - __fsub_rn(z, 12582912.f);
    float p =         1.5403530e-4f;
    p = fmaf(p, f,    1.3333558e-3f);
    p = fmaf(p, f,    9.6181291e-3f);
    p = fmaf(p, f,    5.5504109e-2f);
    p = fmaf(p, f,    2.4022651e-1f);
    p = fmaf(p, f,    6.9314718e-1f);
    p = fmaf(p, f,    1.0f);
    return p * __int_as_float((n + 127) << 23);
}

// ---------------------------------------------------------------------------
// blocks 0..15: M ; 16..63: CT (dot) ; 64..175: transposes WHHT/W1T/W2T
__global__ void k_precomp(const float* __restrict__ Wq,
                          const float* __restrict__ Wk,
                          const float* __restrict__ W_ih,
                          const float* __restrict__ Wv,
                          const float* __restrict__ W_hh,
                          const float* __restrict__ W1,
                          const float* __restrict__ W2) {
    int bi = blockIdx.x, t = threadIdx.x;
    if (bi < 16) {
        int o = bi*256 + t;
        int e = o >> 6, tc = o & 63;
        float acc = 0.f;
        #pragma unroll 8
        for (int d = 0; d < 64; d++)
            acc += Wq[d*64 + e] * Wk[d*64 + tc];
        g_M[e*64 + tc] = acc * SCALE;
    } else if (bi < 64) {
        int o = (bi-16)*256 + t;        // o = e*192 + j
        int e = o / 192, j = o - e*192;
        float acc = 0.f;
        #pragma unroll 8
        for (int h = 0; h < 64; h++)
            acc += W_ih[j*64 + h] * Wv[h*64 + e];
        g_CT[o] = acc;
    } else {
        int idx = (bi-64)*256 + t;
        if (idx < 12288) {
            int e = idx / 192, j = idx - e*192;
            g_WHHT[idx] = W_hh[j*64 + e];
        } else if (idx < 20480) {
            int o = idx - 12288;
            int e = o >> 7, j = o & 127;
            g_W1T[o] = W1[j*64 + e];
        } else {
            int o = idx - 20480;
            int j = o >> 6, d = o & 63;
            g_W2T[o] = W2[d*128 + j];
        }
    }
}

// ---------------------------------------------------------------------------
// init slots + initial q prep + zero accumulators (merged)
__global__ void k_q0(const float* __restrict__ noise,
                     const float* __restrict__ mu,
                     const float* __restrict__ logsig,
                     const float* __restrict__ lnw,
                     const float* __restrict__ lnb,
                     const float* __restrict__ w_in,
                     const float* __restrict__ b_in) {
    int b = blockIdx.x;
    int tid = threadIdx.x;
    int w = tid >> 5, lane = tid & 31;
    __shared__ float sl[SS*64];
    __shared__ float sn[SS*64];
    __shared__ float qtmp[SS*64];

    for (int i = tid; i < SS*64; i += 256) {
        int d = i & 63;
        float v = mu[d] + expf(logsig[d]) * noise[b*SS*64 + i];
        g_slots[b*SS*64 + i] = v;
        sl[i] = v;
        g_u[b*SS*64 + i] = 0.f;
    }
    if (tid < SS) { g_den[b*SS + tid] = 0.f; g_c2[b*SS + tid] = 0.f; }
    __syncthreads();

    if (w < SS) {
        float v0 = sl[w*64 + lane], v1 = sl[w*64 + lane+32];
        float sum = v0 + v1, sq = v0*v0 + v1*v1;
        #pragma unroll
        for (int o = 16; o; o >>= 1) {
            sum += __shfl_xor_sync(0xffffffffu, sum, o);
            sq  += __shfl_xor_sync(0xffffffffu, sq,  o);
        }
        float mean = sum * (1.f/64.f);
        float var  = sq  * (1.f/64.f) - mean*mean;
        float rstd = rsqrtf(var + LN_EPS);
        sn[w*64 + lane]    = (v0 - mean)*rstd*lnw[lane]    + lnb[lane];
        sn[w*64 + lane+32] = (v1 - mean)*rstd*lnw[lane+32] + lnb[lane+32];
    }
    __syncthreads();

    for (int i = tid; i < SS*64; i += 256) {
        int s = i >> 6, tc = i & 63;
        float acc = 0.f;
        #pragma unroll 8
        for (int e = 0; e < 64; e++)
            acc += sn[s*64 + e] * g_M[e*64 + tc];
        qtmp[i] = acc;
        g_qt[b*SS*64 + i] = acc * w_in[tc];
    }
    __syncthreads();
    if (tid < 14) {
        int s = tid >> 1;
        float acc = 0.f;
        if ((tid & 1) == 0) {
            for (int tc = 0; tc < 64; tc++) acc += qtmp[s*64+tc] * w_in[tc];
        } else {
            for (int tc = 0; tc < 64; tc++) acc += qtmp[s*64+tc] * b_in[tc];
        }
        g_qsc[b*SS*2 + tid] = acc;
    }
}

// ---------------------------------------------------------------------------
// Streaming pass + embedded per-batch finalize (last block of each batch).
// smem floats: xs 4*2176 | qw 448 | qsc 16 | psr 4*512
#define AT_XS   0
#define AT_QW   8704
#define AT_QSC  9152
#define AT_PSR  9168
#define AT_TOT  11216

// finalize smem offsets (reuse attn smem after sync)
#define F_UPD  0
#define F_PREV 448
#define F_GI   896
#define F_GH   2240
#define F_ACT  3584
#define F_MLN  4032
#define F_H1   4480
#define F_RED  5376

__global__ void __launch_bounds__(128) k_attn(
        const float* __restrict__ inputs,
        const float* __restrict__ b_ih, const float* __restrict__ b_hh,
        const float* __restrict__ b1,  const float* __restrict__ b2,
        const float* __restrict__ ln_mlp_w, const float* __restrict__ ln_mlp_b,
        const float* __restrict__ ln_slots_w, const float* __restrict__ ln_slots_b,
        const float* __restrict__ ln_in_w, const float* __restrict__ ln_in_b,
        float* __restrict__ out, int last) {
    extern __shared__ float smf[];
    __shared__ int tkt;
    int b = blockIdx.y, tile = blockIdx.x;
    int tid = threadIdx.x;
    int w = tid >> 5, lane = tid & 31;

    for (int i = tid; i < SS*64; i += 128) smf[AT_QW + i] = g_qt[b*SS*64 + i];
    if (tid < 14) smf[AT_QSC + tid] = g_qsc[b*14 + tid];

    float4* xsw = (float4*)(smf + AT_XS + w*2176);
    const float4* src4 = (const float4*)(inputs +
                         ((size_t)b*NN + (size_t)tile*128 + w*32) * DD);
    #pragma unroll
    for (int k = 0; k < 16; k++) {
        int idx = lane + 32*k;
        xsw[(idx >> 4)*17 + (idx & 15)] = src4[idx];
    }
    __syncthreads();

    // phase A: token per thread (t = lane), packed f32x2 math, float4 qw loads
    {
        const float4* row = xsw + lane*17;
        const float4* qw4 = (const float4*)(smf + AT_QW);
        u64 dot2[SS];
        #pragma unroll
        for (int s = 0; s < SS; s++) dot2[s] = 0;
        u64 sum2 = 0, sq2 = 0;
        #pragma unroll
        for (int k = 0; k < 16; k++) {
            float4 v = row[k];
            u64 a = pk(v.x, v.y), c = pk(v.z, v.w);
            add2(sum2, a); add2(sum2, c);
            fma2(sq2, a, a); fma2(sq2, c, c);
            #pragma unroll
            for (int s = 0; s < SS; s++) {
                float4 qv = qw4[s*16 + k];
                fma2(dot2[s], a, pk(qv.x, qv.y));
                fma2(dot2[s], c, pk(qv.z, qv.w));
            }
        }
        float lo, hi;
        upk(sum2, lo, hi); float sum = lo + hi;
        upk(sq2,  lo, hi); float sq  = lo + hi;
        float m = sum * (1.f/64.f);
        float vr = fmaf(sq, 1.f/64.f, -m*m) + LN_EPS;
        float r = rsqrtf(vr);
        float inv_r = vr * r;

        float lg[SS];
        #pragma unroll
        for (int s = 0; s < SS; s++) {
            upk(dot2[s], lo, hi);
            float d = lo + hi;
            float t1 = fmaf(-m, smf[AT_QSC + 2*s], d);
            lg[s] = fmaf(r, t1, smf[AT_QSC + 2*s + 1]);
        }
        float mx = lg[0];
        #pragma unroll
        for (int s = 1; s < SS; s++) mx = fmaxf(mx, lg[s]);
        float ex[SS], tot = 0.f;
        #pragma unroll
        for (int s = 0; s < SS; s++) { ex[s] = fexp(lg[s] - mx); tot += ex[s]; }
        float inv = __fdividef(1.f, tot);

        u64* psr = (u64*)(smf + AT_PSR) + w*256 + lane*8;
        #pragma unroll
        for (int s = 0; s < SS; s++) {
            float p  = fmaf(ex[s], inv, EPSV);
            float pr = p * r;
            psr[s] = pk(pr, pr);
        }
        psr[7] = pk(inv_r, m);
    }
    __syncwarp();

    // den / c2 (lanes 0..13): p = pr*inv_r, c2 term = pr*m
    if (lane < 14) {
        int s7 = (lane < 7) ? lane : lane - 7;
        int hf = (lane < 7) ? 0 : 1;
        const float* base = smf + AT_PSR + w*512;
        float val = 0.f;
        #pragma unroll
        for (int t = 0; t < 32; t++)
            val += base[(t*8 + s7)*2] * base[t*16 + 14 + hf];
        if (lane < 7) atomicAdd(&g_den[b*SS + s7], val);
        else          atomicAdd(&g_c2[b*SS + s7],  val);
    }

    // phase B: warp-local outer product, packed; psr read as paired float4
    {
        int h = lane >> 4, e4 = lane & 15;
        const u64* psru = (const u64*)(smf + AT_PSR) + w*256;
        u64 acca[SS], accb[SS];
        #pragma unroll
        for (int s = 0; s < SS; s++) { acca[s] = 0; accb[s] = 0; }
        #pragma unroll
        for (int j = 0; j < 16; j++) {
            int t = 2*j + h;
            float4 xv = xsw[t*17 + e4];
            u64 xa = pk(xv.x, xv.y), xb = pk(xv.z, xv.w);
            const float4* pf = (const float4*)(psru + t*8);
            #pragma unroll
            for (int i = 0; i < 4; i++) {
                float4 pp = pf[i];
                u64 pa = pk(pp.x, pp.y);
                fma2(acca[2*i], xa, pa);
                fma2(accb[2*i], xb, pa);
                if (2*i + 1 < SS) {
                    u64 pb = pk(pp.z, pp.w);
                    fma2(acca[2*i+1], xa, pb);
                    fma2(accb[2*i+1], xb, pb);
                }
            }
        }
        float4* psumw = (float4*)(smf + AT_XS + w*2176);   // reuse own xs
        #pragma unroll
        for (int s = 0; s < SS; s++) {
            u64 oa = __shfl_xor_sync(0xffffffffu, acca[s], 16);
            u64 ob = __shfl_xor_sync(0xffffffffu, accb[s], 16);
            add2(acca[s], oa); add2(accb[s], ob);
            if (h == 0) {
                float4 o;
                upk(acca[s], o.x, o.y);
                upk(accb[s], o.z, o.w);
                psumw[s*16 + e4] = o;
            }
        }
    }
    __syncthreads();

    if (tid < 112) {
        int s = tid >> 4, e4 = tid & 15;
        float4 acc = make_float4(0.f, 0.f, 0.f, 0.f);
        #pragma unroll
        for (int w2 = 0; w2 < 4; w2++) {
            float4 v = ((const float4*)(smf + AT_XS + w2*2176))[s*16 + e4];
            acc.x += v.x; acc.y += v.y; acc.z += v.z; acc.w += v.w;
        }
        float* up = g_u + (b*SS + s)*DD + e4*4;
        atomicAdd(up+0, acc.x); atomicAdd(up+1, acc.y);
        atomicAdd(up+2, acc.z); atomicAdd(up+3, acc.w);
    }

    // ---- ticket: last block of this batch runs the finalize ----
    __threadfence();
    __syncthreads();
    if (tid == 0) tkt = atomicAdd(&g_cnt[b], 1);
    __syncthreads();
    if (tkt != NN/128 - 1) return;

    // ================= embedded finalize (batch b) ======================
    float* F = smf;
    __syncthreads();

    for (int i = tid; i < SS*64; i += 128) {
        int s = i >> 6, e = i & 63;
        float den = __ldcg(&g_den[b*SS + s]);
        float c2  = __ldcg(&g_c2[b*SS + s]);
        float u   = __ldcg(&g_u[b*SS*64 + i]);
        F[F_UPD + i]  = fmaf(ln_in_w[e] * __fdividef(1.f, den), u - c2, ln_in_b[e]);
        F[F_PREV + i] = g_slots[b*SS*64 + i];
    }
    __syncthreads();

    // gi = upd @ C^T + b_ih ; gh = prev @ W_hh^T + b_hh
    for (int i = tid; i < SS*192; i += 128) {
        int s = i / 192, j = i - s*192;
        float ai = b_ih[j], ah = b_hh[j];
        const float* uu = F + F_UPD  + s*64;
        const float* pp = F + F_PREV + s*64;
        #pragma unroll 16
        for (int e = 0; e < 64; e++) {
            ai = fmaf(uu[e], g_CT[e*192 + j],   ai);
            ah = fmaf(pp[e], g_WHHT[e*192 + j], ah);
        }
        F[F_GI + i] = ai;
        F[F_GH + i] = ah;
    }
    __syncthreads();

    // GRU
    for (int i = tid; i < SS*64; i += 128) {
        int s = i >> 6, d = i & 63;
        float r = 1.f/(1.f + __expf(-(F[F_GI + s*192 + d]      + F[F_GH + s*192 + d])));
        float z = 1.f/(1.f + __expf(-(F[F_GI + s*192 + 64 + d] + F[F_GH + s*192 + 64 + d])));
        float n = tanhf(fmaf(r, F[F_GH + s*192 + 128 + d], F[F_GI + s*192 + 128 + d]));
        F[F_ACT + i] = (1.f - z)*n + z*F[F_PREV + i];
    }
    __syncthreads();

    // LN (mlp) stats, serial per slot
    if (tid < SS) {
        float sum = 0.f, sq = 0.f;
        for (int e = 0; e < 64; e++) {
            float v = F[F_ACT + tid*64 + e];
            sum += v; sq += v*v;
        }
        float m = sum * (1.f/64.f);
        float var = sq * (1.f/64.f) - m*m;
        F[F_RED + tid*2]     = m;
        F[F_RED + tid*2 + 1] = rsqrtf(var + LN_EPS);
    }
    __syncthreads();
    for (int i = tid; i < SS*64; i += 128) {
        int s = i >> 6, d = i & 63;
        F[F_MLN + i] = (F[F_ACT + i] - F[F_RED + s*2]) * F[F_RED + s*2+1]
                       * ln_mlp_w[d] + ln_mlp_b[d];
    }
    __syncthreads();

    // h1 = relu(mln @ W1^T + b1)
    for (int i = tid; i < SS*128; i += 128) {
        int s = i >> 7, j = i & 127;
        float acc = b1[j];
        const float* mm = F + F_MLN + s*64;
        #pragma unroll 16
        for (int e = 0; e < 64; e++)
            acc = fmaf(mm[e], g_W1T[e*128 + j], acc);
        F[F_H1 + i] = fmaxf(acc, 0.f);
    }
    __syncthreads();

    // res = newslot + h1 @ W2^T + b2
    for (int i = tid; i < SS*64; i += 128) {
        int s = i >> 6, d = i & 63;
        float acc = b2[d];
        const float* hh = F + F_H1 + s*128;
        #pragma unroll 16
        for (int j = 0; j < 128; j++)
            acc = fmaf(hh[j], g_W2T[j*64 + d], acc);
        float res = F[F_ACT + i] + acc;
        F[F_ACT + i] = res;
        g_slots[b*SS*64 + i] = res;
        if (last) out[b*SS*64 + i] = res;
    }

    if (!last) {
        __syncthreads();
        // next-iteration prep: LN(res) -> qt -> qw/sw/sb ; zero accumulators
        if (tid < SS) {
            float sum = 0.f, sq = 0.f;
            for (int e = 0; e < 64; e++) {
                float v = F[F_ACT + tid*64 + e];
                sum += v; sq += v*v;
            }
            float m = sum * (1.f/64.f);
            float var = sq * (1.f/64.f) - m*m;
            F[F_RED + tid*2]     = m;
            F[F_RED + tid*2 + 1] = rsqrtf(var + LN_EPS);
            g_den[b*SS + tid] = 0.f;
            g_c2[b*SS + tid]  = 0.f;
        }
        for (int i = tid; i < SS*64; i += 128) g_u[b*SS*64 + i] = 0.f;
        __syncthreads();
        for (int i = tid; i < SS*64; i += 128) {
            int s = i >> 6, d = i & 63;
            F[F_MLN + i] = (F[F_ACT + i] - F[F_RED + s*2]) * F[F_RED + s*2+1]
                           * ln_slots_w[d] + ln_slots_b[d];
        }
        __syncthreads();
        for (int i = tid; i < SS*64; i += 128) {
            int s = i >> 6, tc = i & 63;
            float acc = 0.f;
            const float* ss = F + F_MLN + s*64;
            #pragma unroll 16
            for (int e = 0; e < 64; e++)
                acc = fmaf(ss[e], g_M[e*64 + tc], acc);
            F[F_GI + i] = acc;
            g_qt[b*SS*64 + i] = acc * ln_in_w[tc];
        }
        __syncthreads();
        if (tid < 14) {
            int s = tid >> 1;
            float acc = 0.f;
            if ((tid & 1) == 0) {
                for (int tc = 0; tc < 64; tc++) acc += F[F_GI + s*64+tc] * ln_in_w[tc];
            } else {
                for (int tc = 0; tc < 64; tc++) acc += F[F_GI + s*64+tc] * ln_in_b[tc];
            }
            g_qsc[b*14 + tid] = acc;
        }
    }
    __syncthreads();
    if (tid == 0) g_cnt[b] = 0;   // reset for next launch / replay
}

// ---------------------------------------------------------------------------
extern "C" void kernel_launch(void* const* d_in, const int* in_sizes, int n_in,
                              void* d_out, int out_size) {
    const float* inputs     = (const float*)d_in[0];
    const float* noise      = (const float*)d_in[1];
    const float* ln_in_w    = (const float*)d_in[2];
    const float* ln_in_b    = (const float*)d_in[3];
    const float* ln_slots_w = (const float*)d_in[4];
    const float* ln_slots_b = (const float*)d_in[5];
    const float* ln_mlp_w   = (const float*)d_in[6];
    const float* ln_mlp_b   = (const float*)d_in[7];
    const float* mu         = (const float*)d_in[8];
    const float* logsig     = (const float*)d_in[9];
    const float* Wq         = (const float*)d_in[10];
    const float* Wk         = (const float*)d_in[11];
    const float* Wv         = (const float*)d_in[12];
    const float* W_ih       = (const float*)d_in[13];
    const float* W_hh       = (const float*)d_in[14];
    const float* b_ih       = (const float*)d_in[15];
    const float* b_hh       = (const float*)d_in[16];
    const float* W1         = (const float*)d_in[17];
    const float* b1         = (const float*)d_in[18];
    const float* W2         = (const float*)d_in[19];
    const float* b2         = (const float*)d_in[20];
    float* out = (float*)d_out;

    cudaFuncSetAttribute(k_attn, cudaFuncAttributeMaxDynamicSharedMemorySize,
                         AT_TOT*4);

    k_precomp<<<176, 256>>>(Wq, Wk, W_ih, Wv, W_hh, W1, W2);
    k_q0<<<BB, 256>>>(noise, mu, logsig, ln_slots_w, ln_slots_b,
                      ln_in_w, ln_in_b);
    for (int it = 0; it < NUM_ITERS; it++) {
        dim3 grid(NN/128, BB);
        k_attn<<<grid, 128, AT_TOT*4>>>(inputs,
            b_ih, b_hh, b1, b2,
            ln_mlp_w, ln_mlp_b, ln_slots_w, ln_slots_b,
            ln_in_w, ln_in_b,
            out, it == NUM_ITERS - 1 ? 1 : 0);
    }
}

// round 8
// speedup vs baseline: 1.1933x; 1.1933x over previous
#include <cuda_runtime.h>
#include <math.h>

#define BB 128
#define NN 4096
#define DD 64
#define SS 7
#define HH 128
#define NUM_ITERS 3
#define EPSV 1e-8f
#define LN_EPS 1e-5f
#define SCALE 0.125f   // 64^-0.5

typedef unsigned long long u64;

// persistent scratch (no allocation allowed)
__device__ float g_slots[BB*SS*DD];
__device__ float g_qt[BB*SS*DD];    // qw = ln_in_w ⊙ (q@Wk)  [b][s][64]
__device__ float g_qsc[BB*SS*2];    // {sw, sb} per (b,s)
__device__ float g_u[BB*SS*DD];     // G1 = sum_n (p*r) * x
__device__ float g_den[BB*SS];      // sum_n p
__device__ float g_c2[BB*SS];       // sum_n p*r*m
__device__ float g_M[DD*DD];        // scale * Wq^T @ Wk      [e][t]
__device__ float g_CT[DD*3*DD];     // (W_ih @ Wv)^T          [e][j]
__device__ float g_WHHT[DD*3*DD];   // W_hh^T                 [e][j]
__device__ float g_W1T[DD*HH];      // W1^T                   [e][j]
__device__ float g_W2T[HH*DD];      // W2^T                   [j][d]

// ---------------------------------------------------------------------------
__device__ __forceinline__ u64 pk(float lo, float hi){
    u64 r; asm("mov.b64 %0,{%1,%2};" : "=l"(r) : "f"(lo), "f"(hi)); return r;
}
__device__ __forceinline__ void upk(u64 v, float& lo, float& hi){
    asm("mov.b64 {%0,%1},%2;" : "=f"(lo), "=f"(hi) : "l"(v));
}
__device__ __forceinline__ void fma2(u64& d, u64 a, u64 b){
    asm("fma.rn.f32x2 %0,%1,%2,%0;" : "+l"(d) : "l"(a), "l"(b));
}
__device__ __forceinline__ void add2(u64& d, u64 a){
    asm("add.rn.f32x2 %0,%1,%0;" : "+l"(d) : "l"(a));
}
// fast exp: exp2 split with magic bias + degree-6 poly (rel err ~1e-7)
__device__ __forceinline__ float fexp(float x){
    float t = fmaxf(x * 1.4426950408889634f, -126.f);
    float z = __fadd_rn(t, 12582912.f);
    int n = __float_as_int(z) - 0x4B400000;
    float f = t - __fsub_rn(z, 12582912.f);
    float p =         1.5403530e-4f;
    p = fmaf(p, f,    1.3333558e-3f);
    p = fmaf(p, f,    9.6181291e-3f);
    p = fmaf(p, f,    5.5504109e-2f);
    p = fmaf(p, f,    2.4022651e-1f);
    p = fmaf(p, f,    6.9314718e-1f);
    p = fmaf(p, f,    1.0f);
    return p * __int_as_float((n + 127) << 23);
}

// ---------------------------------------------------------------------------
// blocks 0..15: M ; 16..63: CT (dot) ; 64..175: transposes WHHT/W1T/W2T
__global__ void k_precomp(const float* __restrict__ Wq,
                          const float* __restrict__ Wk,
                          const float* __restrict__ W_ih,
                          const float* __restrict__ Wv,
                          const float* __restrict__ W_hh,
                          const float* __restrict__ W1,
                          const float* __restrict__ W2) {
    int bi = blockIdx.x, t = threadIdx.x;
    if (bi < 16) {
        int o = bi*256 + t;
        int e = o >> 6, tc = o & 63;
        float acc = 0.f;
        #pragma unroll 8
        for (int d = 0; d < 64; d++)
            acc += Wq[d*64 + e] * Wk[d*64 + tc];
        g_M[e*64 + tc] = acc * SCALE;
    } else if (bi < 64) {
        int o = (bi-16)*256 + t;        // o = e*192 + j
        int e = o / 192, j = o - e*192;
        float acc = 0.f;
        #pragma unroll 8
        for (int h = 0; h < 64; h++)
            acc += W_ih[j*64 + h] * Wv[h*64 + e];
        g_CT[o] = acc;
    } else {
        int idx = (bi-64)*256 + t;
        if (idx < 12288) {
            int e = idx / 192, j = idx - e*192;
            g_WHHT[idx] = W_hh[j*64 + e];
        } else if (idx < 20480) {
            int o = idx - 12288;
            int e = o >> 7, j = o & 127;
            g_W1T[o] = W1[j*64 + e];
        } else {
            int o = idx - 20480;
            int j = o >> 6, d = o & 63;
            g_W2T[o] = W2[d*128 + j];
        }
    }
}

// ---------------------------------------------------------------------------
// init slots + initial q prep + zero accumulators (merged)
__global__ void k_q0(const float* __restrict__ noise,
                     const float* __restrict__ mu,
                     const float* __restrict__ logsig,
                     const float* __restrict__ lnw,
                     const float* __restrict__ lnb,
                     const float* __restrict__ w_in,
                     const float* __restrict__ b_in) {
    int b = blockIdx.x;
    int tid = threadIdx.x;
    int w = tid >> 5, lane = tid & 31;
    __shared__ float sl[SS*64];
    __shared__ float sn[SS*64];
    __shared__ float qtmp[SS*64];

    for (int i = tid; i < SS*64; i += 256) {
        int d = i & 63;
        float v = mu[d] + expf(logsig[d]) * noise[b*SS*64 + i];
        g_slots[b*SS*64 + i] = v;
        sl[i] = v;
        g_u[b*SS*64 + i] = 0.f;
    }
    if (tid < SS) { g_den[b*SS + tid] = 0.f; g_c2[b*SS + tid] = 0.f; }
    __syncthreads();

    if (w < SS) {
        float v0 = sl[w*64 + lane], v1 = sl[w*64 + lane+32];
        float sum = v0 + v1, sq = v0*v0 + v1*v1;
        #pragma unroll
        for (int o = 16; o; o >>= 1) {
            sum += __shfl_xor_sync(0xffffffffu, sum, o);
            sq  += __shfl_xor_sync(0xffffffffu, sq,  o);
        }
        float mean = sum * (1.f/64.f);
        float var  = sq  * (1.f/64.f) - mean*mean;
        float rstd = rsqrtf(var + LN_EPS);
        sn[w*64 + lane]    = (v0 - mean)*rstd*lnw[lane]    + lnb[lane];
        sn[w*64 + lane+32] = (v1 - mean)*rstd*lnw[lane+32] + lnb[lane+32];
    }
    __syncthreads();

    for (int i = tid; i < SS*64; i += 256) {
        int s = i >> 6, tc = i & 63;
        float acc = 0.f;
        #pragma unroll 8
        for (int e = 0; e < 64; e++)
            acc += sn[s*64 + e] * g_M[e*64 + tc];
        qtmp[i] = acc;
        g_qt[b*SS*64 + i] = acc * w_in[tc];
    }
    __syncthreads();
    if (tid < 14) {
        int s = tid >> 1;
        float acc = 0.f;
        if ((tid & 1) == 0) {
            for (int tc = 0; tc < 64; tc++) acc += qtmp[s*64+tc] * w_in[tc];
        } else {
            for (int tc = 0; tc < 64; tc++) acc += qtmp[s*64+tc] * b_in[tc];
        }
        g_qsc[b*SS*2 + tid] = acc;
    }
}

// ---------------------------------------------------------------------------
// Streaming pass, warp-independent; all smem traffic via LDS.128 (ulonglong2).
// smem floats: xs 4*2176 | qw 448 | qsc 16 | psr 4*512
#define AT_XS   0
#define AT_QW   8704
#define AT_QSC  9152
#define AT_PSR  9168
#define AT_TOT  11216

__global__ void __launch_bounds__(128) k_attn(const float* __restrict__ inputs) {
    extern __shared__ float smf[];
    int b = blockIdx.y, tile = blockIdx.x;
    int tid = threadIdx.x;
    int w = tid >> 5, lane = tid & 31;

    for (int i = tid; i < SS*64; i += 128) smf[AT_QW + i] = g_qt[b*SS*64 + i];
    if (tid < 14) smf[AT_QSC + tid] = g_qsc[b*14 + tid];

    float4* xsw = (float4*)(smf + AT_XS + w*2176);
    const float4* src4 = (const float4*)(inputs +
                         ((size_t)b*NN + (size_t)tile*128 + w*32) * DD);
    #pragma unroll
    for (int k = 0; k < 16; k++) {
        int idx = lane + 32*k;
        xsw[(idx >> 4)*17 + (idx & 15)] = src4[idx];
    }
    __syncthreads();

    // phase A: token per thread (t = lane); packed loads straight from LDS.128
    {
        const ulonglong2* row = (const ulonglong2*)(xsw + lane*17);
        const ulonglong2* qwu = (const ulonglong2*)(smf + AT_QW);
        u64 dot2[SS];
        #pragma unroll
        for (int s = 0; s < SS; s++) dot2[s] = 0;
        u64 sum2 = 0, sq2 = 0;
        #pragma unroll
        for (int k = 0; k < 16; k++) {
            ulonglong2 v = row[k];
            add2(sum2, v.x); add2(sum2, v.y);
            fma2(sq2, v.x, v.x); fma2(sq2, v.y, v.y);
            #pragma unroll
            for (int s = 0; s < SS; s++) {
                ulonglong2 q = qwu[s*16 + k];
                fma2(dot2[s], v.x, q.x);
                fma2(dot2[s], v.y, q.y);
            }
        }
        float lo, hi;
        upk(sum2, lo, hi); float sum = lo + hi;
        upk(sq2,  lo, hi); float sq  = lo + hi;
        float m = sum * (1.f/64.f);
        float vr = fmaf(sq, 1.f/64.f, -m*m) + LN_EPS;
        float r = rsqrtf(vr);
        float inv_r = vr * r;

        float lg[SS];
        #pragma unroll
        for (int s = 0; s < SS; s++) {
            upk(dot2[s], lo, hi);
            float d = lo + hi;
            float t1 = fmaf(-m, smf[AT_QSC + 2*s], d);
            lg[s] = fmaf(r, t1, smf[AT_QSC + 2*s + 1]);
        }
        float mx = lg[0];
        #pragma unroll
        for (int s = 1; s < SS; s++) mx = fmaxf(mx, lg[s]);
        float ex[SS], tot = 0.f;
        #pragma unroll
        for (int s = 0; s < SS; s++) { ex[s] = fexp(lg[s] - mx); tot += ex[s]; }
        float inv = __fdividef(1.f, tot);

        u64* psr = (u64*)(smf + AT_PSR) + w*256 + lane*8;
        #pragma unroll
        for (int s = 0; s < SS; s++) {
            float p  = fmaf(ex[s], inv, EPSV);
            float pr = p * r;
            psr[s] = pk(pr, pr);
        }
        psr[7] = pk(inv_r, m);
    }
    __syncwarp();

    // den / c2 (lanes 0..13): p = pr*inv_r, c2 term = pr*m
    if (lane < 14) {
        int s7 = (lane < 7) ? lane : lane - 7;
        int hf = (lane < 7) ? 0 : 1;
        const float* base = smf + AT_PSR + w*512;
        float val = 0.f;
        #pragma unroll
        for (int t = 0; t < 32; t++)
            val += base[(t*8 + s7)*2] * base[t*16 + 14 + hf];
        if (lane < 7) atomicAdd(&g_den[b*SS + s7], val);
        else          atomicAdd(&g_c2[b*SS + s7],  val);
    }

    // phase B: warp-local outer product; paired LDS.128 for x and psr
    {
        int h = lane >> 4, e4 = lane & 15;
        const u64* psru = (const u64*)(smf + AT_PSR) + w*256;
        u64 acca[SS], accb[SS];
        #pragma unroll
        for (int s = 0; s < SS; s++) { acca[s] = 0; accb[s] = 0; }
        #pragma unroll
        for (int j = 0; j < 16; j++) {
            int t = 2*j + h;
            ulonglong2 xv = *(const ulonglong2*)(xsw + t*17 + e4);
            const ulonglong2* pf = (const ulonglong2*)(psru + t*8);
            #pragma unroll
            for (int i = 0; i < 4; i++) {
                ulonglong2 pp = pf[i];
                fma2(acca[2*i], xv.x, pp.x);
                fma2(accb[2*i], xv.y, pp.x);
                if (2*i + 1 < SS) {
                    fma2(acca[2*i+1], xv.x, pp.y);
                    fma2(accb[2*i+1], xv.y, pp.y);
                }
            }
        }
        float4* psumw = (float4*)(smf + AT_XS + w*2176);   // reuse own xs
        #pragma unroll
        for (int s = 0; s < SS; s++) {
            u64 oa = __shfl_xor_sync(0xffffffffu, acca[s], 16);
            u64 ob = __shfl_xor_sync(0xffffffffu, accb[s], 16);
            add2(acca[s], oa); add2(accb[s], ob);
            if (h == 0) {
                float4 o;
                upk(acca[s], o.x, o.y);
                upk(accb[s], o.z, o.w);
                psumw[s*16 + e4] = o;
            }
        }
    }
    __syncthreads();

    if (tid < 112) {
        int s = tid >> 4, e4 = tid & 15;
        float4 acc = make_float4(0.f, 0.f, 0.f, 0.f);
        #pragma unroll
        for (int w2 = 0; w2 < 4; w2++) {
            float4 v = ((const float4*)(smf + AT_XS + w2*2176))[s*16 + e4];
            acc.x += v.x; acc.y += v.y; acc.z += v.z; acc.w += v.w;
        }
        float* up = g_u + (b*SS + s)*DD + e4*4;
        atomicAdd(up+0, acc.x); atomicAdd(up+1, acc.y);
        atomicAdd(up+2, acc.z); atomicAdd(up+3, acc.w);
    }
}

// ---------------------------------------------------------------------------
// finalize: one block per batch, 448 threads (7 slots × 64). Weights read
// from global; 7-slot reuse makes them L1-hot — 20MB total L2 traffic.
__global__ void __launch_bounds__(448) k_finalize(
        const float* __restrict__ b_ih, const float* __restrict__ b_hh,
        const float* __restrict__ b1,  const float* __restrict__ b2,
        const float* __restrict__ ln_mlp_w, const float* __restrict__ ln_mlp_b,
        const float* __restrict__ ln_slots_w, const float* __restrict__ ln_slots_b,
        const float* __restrict__ ln_in_w, const float* __restrict__ ln_in_b,
        float* __restrict__ out, int last) {
    __shared__ float upd[448], prev[448], gi[1344], gh[1344],
                     act[448], mln[448], h1[896], red[16];
    int b = blockIdx.x;
    int tid = threadIdx.x;
    int w = tid >> 5, lane = tid & 31;
    int s = tid >> 6, d = tid & 63;

    {
        float den = g_den[b*SS + s], c2 = g_c2[b*SS + s];
        upd[tid]  = fmaf(ln_in_w[d] * __fdividef(1.f, den),
                         g_u[b*448 + tid] - c2, ln_in_b[d]);
        prev[tid] = g_slots[b*448 + tid];
    }
    __syncthreads();

    // gi = upd @ C^T + b_ih ; gh = prev @ W_hh^T + b_hh
    for (int i = tid; i < SS*192; i += 448) {
        int ss = i / 192, j = i - ss*192;
        float ai = b_ih[j], ah = b_hh[j];
        const float* uu = upd  + ss*64;
        const float* pp = prev + ss*64;
        #pragma unroll 16
        for (int e = 0; e < 64; e++) {
            ai = fmaf(uu[e], g_CT[e*192 + j],   ai);
            ah = fmaf(pp[e], g_WHHT[e*192 + j], ah);
        }
        gi[i] = ai; gh[i] = ah;
    }
    __syncthreads();

    // GRU
    {
        float r = 1.f/(1.f + __expf(-(gi[s*192 + d]      + gh[s*192 + d])));
        float z = 1.f/(1.f + __expf(-(gi[s*192 + 64 + d] + gh[s*192 + 64 + d])));
        float n = tanhf(fmaf(r, gh[s*192 + 128 + d], gi[s*192 + 128 + d]));
        act[tid] = (1.f - z)*n + z*prev[tid];
    }
    __syncthreads();

    // LN (mlp) stats: warps 0..6, warp w handles slot w
    if (w < SS) {
        float v0 = act[w*64 + lane], v1 = act[w*64 + lane+32];
        float sum = v0 + v1, sq = v0*v0 + v1*v1;
        #pragma unroll
        for (int o = 16; o; o >>= 1) {
            sum += __shfl_xor_sync(0xffffffffu, sum, o);
            sq  += __shfl_xor_sync(0xffffffffu, sq,  o);
        }
        float m = sum * (1.f/64.f);
        float var = sq * (1.f/64.f) - m*m;
        if (lane == 0) { red[w*2] = m; red[w*2+1] = rsqrtf(var + LN_EPS); }
    }
    __syncthreads();
    mln[tid] = (act[tid] - red[s*2]) * red[s*2+1] * ln_mlp_w[d] + ln_mlp_b[d];
    __syncthreads();

    // h1 = relu(mln @ W1^T + b1)
    for (int i = tid; i < SS*128; i += 448) {
        int ss = i >> 7, j = i & 127;
        float acc = b1[j];
        const float* mm = mln + ss*64;
        #pragma unroll 16
        for (int e = 0; e < 64; e++)
            acc = fmaf(mm[e], g_W1T[e*128 + j], acc);
        h1[i] = fmaxf(acc, 0.f);
    }
    __syncthreads();

    // res = newslot + h1 @ W2^T + b2
    float res;
    {
        float acc = b2[d];
        const float* hh = h1 + s*128;
        #pragma unroll 16
        for (int j = 0; j < 128; j++)
            acc = fmaf(hh[j], g_W2T[j*64 + d], acc);
        res = act[tid] + acc;
        act[tid] = res;
        g_slots[b*448 + tid] = res;
        if (last) out[b*448 + tid] = res;
    }
    if (last) return;
    __syncthreads();

    // next-iteration prep: LN(res) -> qt -> qw/sw/sb ; zero accumulators
    if (w < SS) {
        float v0 = act[w*64 + lane], v1 = act[w*64 + lane+32];
        float sum = v0 + v1, sq = v0*v0 + v1*v1;
        #pragma unroll
        for (int o = 16; o; o >>= 1) {
            sum += __shfl_xor_sync(0xffffffffu, sum, o);
            sq  += __shfl_xor_sync(0xffffffffu, sq,  o);
        }
        float m = sum * (1.f/64.f);
        float var = sq * (1.f/64.f) - m*m;
        if (lane == 0) { red[w*2] = m; red[w*2+1] = rsqrtf(var + LN_EPS); }
    }
    g_u[b*448 + tid] = 0.f;
    if (tid < SS) { g_den[b*SS + tid] = 0.f; g_c2[b*SS + tid] = 0.f; }
    __syncthreads();
    mln[tid] = (act[tid] - red[s*2]) * red[s*2+1] * ln_slots_w[d] + ln_slots_b[d];
    __syncthreads();

    {
        float acc = 0.f;
        const float* ssv = mln + s*64;
        #pragma unroll 16
        for (int e = 0; e < 64; e++)
            acc = fmaf(ssv[e], g_M[e*64 + d], acc);
        gi[tid] = acc;                       // reuse gi as qtmp
        g_qt[b*448 + tid] = acc * ln_in_w[d];
    }
    __syncthreads();
    if (tid < 14) {
        int s7 = tid >> 1;
        float acc = 0.f;
        if ((tid & 1) == 0) {
            for (int tc = 0; tc < 64; tc++) acc += gi[s7*64+tc] * ln_in_w[tc];
        } else {
            for (int tc = 0; tc < 64; tc++) acc += gi[s7*64+tc] * ln_in_b[tc];
        }
        g_qsc[b*14 + tid] = acc;
    }
}

// ---------------------------------------------------------------------------
extern "C" void kernel_launch(void* const* d_in, const int* in_sizes, int n_in,
                              void* d_out, int out_size) {
    const float* inputs     = (const float*)d_in[0];
    const float* noise      = (const float*)d_in[1];
    const float* ln_in_w    = (const float*)d_in[2];
    const float* ln_in_b    = (const float*)d_in[3];
    const float* ln_slots_w = (const float*)d_in[4];
    const float* ln_slots_b = (const float*)d_in[5];
    const float* ln_mlp_w   = (const float*)d_in[6];
    const float* ln_mlp_b   = (const float*)d_in[7];
    const float* mu         = (const float*)d_in[8];
    const float* logsig     = (const float*)d_in[9];
    const float* Wq         = (const float*)d_in[10];
    const float* Wk         = (const float*)d_in[11];
    const float* Wv         = (const float*)d_in[12];
    const float* W_ih       = (const float*)d_in[13];
    const float* W_hh       = (const float*)d_in[14];
    const float* b_ih       = (const float*)d_in[15];
    const float* b_hh       = (const float*)d_in[16];
    const float* W1         = (const float*)d_in[17];
    const float* b1         = (const float*)d_in[18];
    const float* W2         = (const float*)d_in[19];
    const float* b2         = (const float*)d_in[20];
    float* out = (float*)d_out;

    cudaFuncSetAttribute(k_attn, cudaFuncAttributeMaxDynamicSharedMemorySize,
                         AT_TOT*4);

    k_precomp<<<176, 256>>>(Wq, Wk, W_ih, Wv, W_hh, W1, W2);
    k_q0<<<BB, 256>>>(noise, mu, logsig, ln_slots_w, ln_slots_b,
                      ln_in_w, ln_in_b);
    for (int it = 0; it < NUM_ITERS; it++) {
        dim3 grid(NN/128, BB);
        k_attn<<<grid, 128, AT_TOT*4>>>(inputs);
        k_finalize<<<BB, 448>>>(b_ih, b_hh, b1, b2,
                                ln_mlp_w, ln_mlp_b, ln_slots_w, ln_slots_b,
                                ln_in_w, ln_in_b,
                                out, it == NUM_ITERS - 1 ? 1 : 0);
    }
}

// round 9
// speedup vs baseline: 1.5240x; 1.2771x over previous
#include <cuda_runtime.h>
#include <math.h>

#define BB 128
#define NN 4096
#define DD 64
#define SS 7
#define HH 128
#define NUM_ITERS 3
#define EPSV 1e-8f
#define LN_EPS 1e-5f
#define SCALE 0.125f   // 64^-0.5

typedef unsigned long long u64;

// persistent scratch (no allocation allowed)
__device__ float g_slots[BB*SS*DD];
__device__ float g_qt[BB*SS*DD];    // qw = ln_in_w ⊙ (q@Wk)  [b][s][64]
__device__ float g_qsc[BB*SS*2];    // {sw, sb} per (b,s)
__device__ float g_u[BB*SS*DD];     // G1 = sum_n (p*r) * x
__device__ float g_den[BB*SS];      // sum_n p
__device__ float g_c2[BB*SS];       // sum_n p*r*m
__device__ float g_M[DD*DD];        // scale * Wq^T @ Wk      [e][t]
__device__ float g_CT[DD*3*DD];     // (W_ih @ Wv)^T          [e][j]
__device__ float g_WHHT[DD*3*DD];   // W_hh^T                 [e][j]
__device__ float g_W1T[DD*HH];      // W1^T                   [e][j]
__device__ float g_W2T[HH*DD];      // W2^T                   [j][d]

// ---------------------------------------------------------------------------
__device__ __forceinline__ u64 pk(float lo, float hi){
    u64 r; asm("mov.b64 %0,{%1,%2};" : "=l"(r) : "f"(lo), "f"(hi)); return r;
}
__device__ __forceinline__ void upk(u64 v, float& lo, float& hi){
    asm("mov.b64 {%0,%1},%2;" : "=f"(lo), "=f"(hi) : "l"(v));
}
__device__ __forceinline__ void fma2(u64& d, u64 a, u64 b){
    asm("fma.rn.f32x2 %0,%1,%2,%0;" : "+l"(d) : "l"(a), "l"(b));
}
__device__ __forceinline__ void add2(u64& d, u64 a){
    asm("add.rn.f32x2 %0,%1,%0;" : "+l"(d) : "l"(a));
}
// fast exp: exp2 split with magic bias + degree-6 poly (rel err ~1e-7)
__device__ __forceinline__ float fexp(float x){
    float t = fmaxf(x * 1.4426950408889634f, -126.f);
    float z = __fadd_rn(t, 12582912.f);
    int n = __float_as_int(z) - 0x4B400000;
    float f = t - __fsub_rn(z, 12582912.f);
    float p =         1.5403530e-4f;
    p = fmaf(p, f,    1.3333558e-3f);
    p = fmaf(p, f,    9.6181291e-3f);
    p = fmaf(p, f,    5.5504109e-2f);
    p = fmaf(p, f,    2.4022651e-1f);
    p = fmaf(p, f,    6.9314718e-1f);
    p = fmaf(p, f,    1.0f);
    return p * __int_as_float((n + 127) << 23);
}

// ---------------------------------------------------------------------------
// blocks 0..15: M ; 16..63: CT (dot) ; 64..175: transposes WHHT/W1T/W2T
__global__ void k_precomp(const float* __restrict__ Wq,
                          const float* __restrict__ Wk,
                          const float* __restrict__ W_ih,
                          const float* __restrict__ Wv,
                          const float* __restrict__ W_hh,
                          const float* __restrict__ W1,
                          const float* __restrict__ W2) {
    int bi = blockIdx.x, t = threadIdx.x;
    if (bi < 16) {
        int o = bi*256 + t;
        int e = o >> 6, tc = o & 63;
        float acc = 0.f;
        #pragma unroll 8
        for (int d = 0; d < 64; d++)
            acc += Wq[d*64 + e] * Wk[d*64 + tc];
        g_M[e*64 + tc] = acc * SCALE;
    } else if (bi < 64) {
        int o = (bi-16)*256 + t;        // o = e*192 + j
        int e = o / 192, j = o - e*192;
        float acc = 0.f;
        #pragma unroll 8
        for (int h = 0; h < 64; h++)
            acc += W_ih[j*64 + h] * Wv[h*64 + e];
        g_CT[o] = acc;
    } else {
        int idx = (bi-64)*256 + t;
        if (idx < 12288) {
            int e = idx / 192, j = idx - e*192;
            g_WHHT[idx] = W_hh[j*64 + e];
        } else if (idx < 20480) {
            int o = idx - 12288;
            int e = o >> 7, j = o & 127;
            g_W1T[o] = W1[j*64 + e];
        } else {
            int o = idx - 20480;
            int j = o >> 6, d = o & 63;
            g_W2T[o] = W2[d*128 + j];
        }
    }
}

// ---------------------------------------------------------------------------
// init slots + initial q prep + zero accumulators (merged)
__global__ void k_q0(const float* __restrict__ noise,
                     const float* __restrict__ mu,
                     const float* __restrict__ logsig,
                     const float* __restrict__ lnw,
                     const float* __restrict__ lnb,
                     const float* __restrict__ w_in,
                     const float* __restrict__ b_in) {
    int b = blockIdx.x;
    int tid = threadIdx.x;
    int w = tid >> 5, lane = tid & 31;
    __shared__ float sl[SS*64];
    __shared__ float sn[SS*64];
    __shared__ float qtmp[SS*64];

    for (int i = tid; i < SS*64; i += 256) {
        int d = i & 63;
        float v = mu[d] + expf(logsig[d]) * noise[b*SS*64 + i];
        g_slots[b*SS*64 + i] = v;
        sl[i] = v;
        g_u[b*SS*64 + i] = 0.f;
    }
    if (tid < SS) { g_den[b*SS + tid] = 0.f; g_c2[b*SS + tid] = 0.f; }
    __syncthreads();

    if (w < SS) {
        float v0 = sl[w*64 + lane], v1 = sl[w*64 + lane+32];
        float sum = v0 + v1, sq = v0*v0 + v1*v1;
        #pragma unroll
        for (int o = 16; o; o >>= 1) {
            sum += __shfl_xor_sync(0xffffffffu, sum, o);
            sq  += __shfl_xor_sync(0xffffffffu, sq,  o);
        }
        float mean = sum * (1.f/64.f);
        float var  = sq  * (1.f/64.f) - mean*mean;
        float rstd = rsqrtf(var + LN_EPS);
        sn[w*64 + lane]    = (v0 - mean)*rstd*lnw[lane]    + lnb[lane];
        sn[w*64 + lane+32] = (v1 - mean)*rstd*lnw[lane+32] + lnb[lane+32];
    }
    __syncthreads();

    for (int i = tid; i < SS*64; i += 256) {
        int s = i >> 6, tc = i & 63;
        float acc = 0.f;
        #pragma unroll 8
        for (int e = 0; e < 64; e++)
            acc += sn[s*64 + e] * g_M[e*64 + tc];
        qtmp[i] = acc;
        g_qt[b*SS*64 + i] = acc * w_in[tc];
    }
    __syncthreads();
    if (tid < 14) {
        int s = tid >> 1;
        float acc = 0.f;
        if ((tid & 1) == 0) {
            for (int tc = 0; tc < 64; tc++) acc += qtmp[s*64+tc] * w_in[tc];
        } else {
            for (int tc = 0; tc < 64; tc++) acc += qtmp[s*64+tc] * b_in[tc];
        }
        g_qsc[b*SS*2 + tid] = acc;
    }
}

// ---------------------------------------------------------------------------
// Streaming pass, warp-independent; all smem traffic via LDS.128 (ulonglong2).
// smem floats: xs 4*2176 | qw 448 | qsc 16 | psr 4*512
#define AT_XS   0
#define AT_QW   8704
#define AT_QSC  9152
#define AT_PSR  9168
#define AT_TOT  11216

__global__ void __launch_bounds__(128) k_attn(const float* __restrict__ inputs) {
    extern __shared__ float smf[];
    int b = blockIdx.y, tile = blockIdx.x;
    int tid = threadIdx.x;
    int w = tid >> 5, lane = tid & 31;

    for (int i = tid; i < SS*64; i += 128) smf[AT_QW + i] = g_qt[b*SS*64 + i];
    if (tid < 14) smf[AT_QSC + tid] = g_qsc[b*14 + tid];

    float4* xsw = (float4*)(smf + AT_XS + w*2176);
    const float4* src4 = (const float4*)(inputs +
                         ((size_t)b*NN + (size_t)tile*128 + w*32) * DD);
    #pragma unroll
    for (int k = 0; k < 16; k++) {
        int idx = lane + 32*k;
        xsw[(idx >> 4)*17 + (idx & 15)] = src4[idx];
    }
    __syncthreads();

    // phase A: token per thread (t = lane); packed loads straight from LDS.128
    {
        const ulonglong2* row = (const ulonglong2*)(xsw + lane*17);
        const ulonglong2* qwu = (const ulonglong2*)(smf + AT_QW);
        u64 dot2[SS];
        #pragma unroll
        for (int s = 0; s < SS; s++) dot2[s] = 0;
        u64 sum2 = 0, sq2 = 0;
        #pragma unroll
        for (int k = 0; k < 16; k++) {
            ulonglong2 v = row[k];
            add2(sum2, v.x); add2(sum2, v.y);
            fma2(sq2, v.x, v.x); fma2(sq2, v.y, v.y);
            #pragma unroll
            for (int s = 0; s < SS; s++) {
                ulonglong2 q = qwu[s*16 + k];
                fma2(dot2[s], v.x, q.x);
                fma2(dot2[s], v.y, q.y);
            }
        }
        float lo, hi;
        upk(sum2, lo, hi); float sum = lo + hi;
        upk(sq2,  lo, hi); float sq  = lo + hi;
        float m = sum * (1.f/64.f);
        float vr = fmaf(sq, 1.f/64.f, -m*m) + LN_EPS;
        float r = rsqrtf(vr);
        float inv_r = vr * r;

        float lg[SS];
        #pragma unroll
        for (int s = 0; s < SS; s++) {
            upk(dot2[s], lo, hi);
            float d = lo + hi;
            float t1 = fmaf(-m, smf[AT_QSC + 2*s], d);
            lg[s] = fmaf(r, t1, smf[AT_QSC + 2*s + 1]);
        }
        float mx = lg[0];
        #pragma unroll
        for (int s = 1; s < SS; s++) mx = fmaxf(mx, lg[s]);
        float ex[SS], tot = 0.f;
        #pragma unroll
        for (int s = 0; s < SS; s++) { ex[s] = fexp(lg[s] - mx); tot += ex[s]; }
        float inv = __fdividef(1.f, tot);

        u64* psr = (u64*)(smf + AT_PSR) + w*256 + lane*8;
        #pragma unroll
        for (int s = 0; s < SS; s++) {
            float p  = fmaf(ex[s], inv, EPSV);
            float pr = p * r;
            psr[s] = pk(pr, pr);
        }
        psr[7] = pk(inv_r, m);
    }
    __syncwarp();

    // den / c2 (lanes 0..13): p = pr*inv_r, c2 term = pr*m
    if (lane < 14) {
        int s7 = (lane < 7) ? lane : lane - 7;
        int hf = (lane < 7) ? 0 : 1;
        const float* base = smf + AT_PSR + w*512;
        float val = 0.f;
        #pragma unroll
        for (int t = 0; t < 32; t++)
            val += base[(t*8 + s7)*2] * base[t*16 + 14 + hf];
        if (lane < 7) atomicAdd(&g_den[b*SS + s7], val);
        else          atomicAdd(&g_c2[b*SS + s7],  val);
    }

    // phase B: warp-local outer product; paired LDS.128 for x and psr
    {
        int h = lane >> 4, e4 = lane & 15;
        const u64* psru = (const u64*)(smf + AT_PSR) + w*256;
        u64 acca[SS], accb[SS];
        #pragma unroll
        for (int s = 0; s < SS; s++) { acca[s] = 0; accb[s] = 0; }
        #pragma unroll
        for (int j = 0; j < 16; j++) {
            int t = 2*j + h;
            ulonglong2 xv = *(const ulonglong2*)(xsw + t*17 + e4);
            const ulonglong2* pf = (const ulonglong2*)(psru + t*8);
            #pragma unroll
            for (int i = 0; i < 4; i++) {
                ulonglong2 pp = pf[i];
                fma2(acca[2*i], xv.x, pp.x);
                fma2(accb[2*i], xv.y, pp.x);
                if (2*i + 1 < SS) {
                    fma2(acca[2*i+1], xv.x, pp.y);
                    fma2(accb[2*i+1], xv.y, pp.y);
                }
            }
        }
        float4* psumw = (float4*)(smf + AT_XS + w*2176);   // reuse own xs
        #pragma unroll
        for (int s = 0; s < SS; s++) {
            u64 oa = __shfl_xor_sync(0xffffffffu, acca[s], 16);
            u64 ob = __shfl_xor_sync(0xffffffffu, accb[s], 16);
            add2(acca[s], oa); add2(accb[s], ob);
            if (h == 0) {
                float4 o;
                upk(acca[s], o.x, o.y);
                upk(accb[s], o.z, o.w);
                psumw[s*16 + e4] = o;
            }
        }
    }
    __syncthreads();

    if (tid < 112) {
        int s = tid >> 4, e4 = tid & 15;
        float4 acc = make_float4(0.f, 0.f, 0.f, 0.f);
        #pragma unroll
        for (int w2 = 0; w2 < 4; w2++) {
            float4 v = ((const float4*)(smf + AT_XS + w2*2176))[s*16 + e4];
            acc.x += v.x; acc.y += v.y; acc.z += v.z; acc.w += v.w;
        }
        float* up = g_u + (b*SS + s)*DD + e4*4;
        atomicAdd(up+0, acc.x); atomicAdd(up+1, acc.y);
        atomicAdd(up+2, acc.z); atomicAdd(up+3, acc.w);
    }
}

// ---------------------------------------------------------------------------
// finalize: one block per (batch, slot) = 896 blocks, 192 threads.
// (measured-good round-6 version: 6 blocks/SM hide weight-load latency)
__global__ void __launch_bounds__(192) k_finalize(
        const float* __restrict__ b_ih, const float* __restrict__ b_hh,
        const float* __restrict__ b1,  const float* __restrict__ b2,
        const float* __restrict__ ln_mlp_w, const float* __restrict__ ln_mlp_b,
        const float* __restrict__ ln_slots_w, const float* __restrict__ ln_slots_b,
        const float* __restrict__ ln_in_w, const float* __restrict__ ln_in_b,
        float* __restrict__ out, int last) {
    __shared__ float upd[64], prev[64], giv[192], ghv[192],
                     act[64], mln[64], h1[128], red[8];
    int bs = blockIdx.x;
    int tid = threadIdx.x;

    if (tid < 64) {
        float invden = __fdividef(1.f, g_den[bs]);
        upd[tid] = fmaf(ln_in_w[tid]*invden, g_u[bs*64 + tid] - g_c2[bs],
                        ln_in_b[tid]);
        prev[tid] = g_slots[bs*64 + tid];
    }
    __syncthreads();

    // gi = upd@C^T + b_ih ; gh = prev@W_hh^T + b_hh  (1 output per thread)
    {
        float ai = b_ih[tid], ah = b_hh[tid];
        #pragma unroll 16
        for (int e = 0; e < 64; e++) {
            ai = fmaf(upd[e],  g_CT[e*192 + tid],   ai);
            ah = fmaf(prev[e], g_WHHT[e*192 + tid], ah);
        }
        giv[tid] = ai; ghv[tid] = ah;
    }
    __syncthreads();

    // GRU + LN partials
    if (tid < 64) {
        float r = 1.f/(1.f + __expf(-(giv[tid]     + ghv[tid])));
        float z = 1.f/(1.f + __expf(-(giv[64+tid]  + ghv[64+tid])));
        float n = tanhf(fmaf(r, ghv[128+tid], giv[128+tid]));
        float v = (1.f - z)*n + z*prev[tid];
        act[tid] = v;
        float sum = v, sq = v*v;
        #pragma unroll
        for (int o = 16; o; o >>= 1) {
            sum += __shfl_xor_sync(0xffffffffu, sum, o);
            sq  += __shfl_xor_sync(0xffffffffu, sq,  o);
        }
        if ((tid & 31) == 0) { red[(tid>>5)*2] = sum; red[(tid>>5)*2+1] = sq; }
    }
    __syncthreads();

    if (tid < 64) {
        float sum = red[0] + red[2], sq = red[1] + red[3];
        float m = sum * (1.f/64.f);
        float var = sq * (1.f/64.f) - m*m;
        float r = rsqrtf(var + LN_EPS);
        mln[tid] = (act[tid] - m)*r*ln_mlp_w[tid] + ln_mlp_b[tid];
    }
    __syncthreads();

    if (tid < 128) {
        float acc = b1[tid];
        #pragma unroll 16
        for (int e = 0; e < 64; e++)
            acc = fmaf(mln[e], g_W1T[e*128 + tid], acc);
        h1[tid] = fmaxf(acc, 0.f);
    }
    __syncthreads();

    float res = 0.f;
    if (tid < 64) {
        float acc = b2[tid];
        #pragma unroll 16
        for (int j = 0; j < 128; j++)
            acc = fmaf(h1[j], g_W2T[j*64 + tid], acc);
        res = act[tid] + acc;
        g_slots[bs*64 + tid] = res;
        if (last) out[bs*64 + tid] = res;
    }
    if (last) return;
    __syncthreads();

    // next-iteration prep: LN(res) -> qt -> qw/sw/sb ; zero accumulators
    if (tid < 64) {
        float sum = res, sq = res*res;
        #pragma unroll
        for (int o = 16; o; o >>= 1) {
            sum += __shfl_xor_sync(0xffffffffu, sum, o);
            sq  += __shfl_xor_sync(0xffffffffu, sq,  o);
        }
        if ((tid & 31) == 0) { red[(tid>>5)*2] = sum; red[(tid>>5)*2+1] = sq; }
        g_u[bs*64 + tid] = 0.f;
    }
    if (tid == 0) { g_den[bs] = 0.f; g_c2[bs] = 0.f; }
    __syncthreads();

    if (tid < 64) {
        float sum = red[0] + red[2], sq = red[1] + red[3];
        float m = sum * (1.f/64.f);
        float var = sq * (1.f/64.f) - m*m;
        float r = rsqrtf(var + LN_EPS);
        mln[tid] = (res - m)*r*ln_slots_w[tid] + ln_slots_b[tid];   // reuse mln as sn
    }
    __syncthreads();

    if (tid < 64) {
        float acc = 0.f;
        #pragma unroll 16
        for (int e = 0; e < 64; e++)
            acc = fmaf(mln[e], g_M[e*64 + tid], acc);
        g_qt[bs*64 + tid] = acc * ln_in_w[tid];
        float pa = acc * ln_in_w[tid];
        float pb = acc * ln_in_b[tid];
        #pragma unroll
        for (int o = 16; o; o >>= 1) {
            pa += __shfl_xor_sync(0xffffffffu, pa, o);
            pb += __shfl_xor_sync(0xffffffffu, pb, o);
        }
        if ((tid & 31) == 0) { red[(tid>>5)*2] = pa; red[(tid>>5)*2+1] = pb; }
    }
    __syncthreads();
    if (tid == 0) {
        g_qsc[bs*2 + 0] = red[0] + red[2];
        g_qsc[bs*2 + 1] = red[1] + red[3];
    }
}

// ---------------------------------------------------------------------------
extern "C" void kernel_launch(void* const* d_in, const int* in_sizes, int n_in,
                              void* d_out, int out_size) {
    const float* inputs     = (const float*)d_in[0];
    const float* noise      = (const float*)d_in[1];
    const float* ln_in_w    = (const float*)d_in[2];
    const float* ln_in_b    = (const float*)d_in[3];
    const float* ln_slots_w = (const float*)d_in[4];
    const float* ln_slots_b = (const float*)d_in[5];
    const float* ln_mlp_w   = (const float*)d_in[6];
    const float* ln_mlp_b   = (const float*)d_in[7];
    const float* mu         = (const float*)d_in[8];
    const float* logsig     = (const float*)d_in[9];
    const float* Wq         = (const float*)d_in[10];
    const float* Wk         = (const float*)d_in[11];
    const float* Wv         = (const float*)d_in[12];
    const float* W_ih       = (const float*)d_in[13];
    const float* W_hh       = (const float*)d_in[14];
    const float* b_ih       = (const float*)d_in[15];
    const float* b_hh       = (const float*)d_in[16];
    const float* W1         = (const float*)d_in[17];
    const float* b1         = (const float*)d_in[18];
    const float* W2         = (const float*)d_in[19];
    const float* b2         = (const float*)d_in[20];
    float* out = (float*)d_out;

    cudaFuncSetAttribute(k_attn, cudaFuncAttributeMaxDynamicSharedMemorySize,
                         AT_TOT*4);

    k_precomp<<<176, 256>>>(Wq, Wk, W_ih, Wv, W_hh, W1, W2);
    k_q0<<<BB, 256>>>(noise, mu, logsig, ln_slots_w, ln_slots_b,
                      ln_in_w, ln_in_b);
    for (int it = 0; it < NUM_ITERS; it++) {
        dim3 grid(NN/128, BB);
        k_attn<<<grid, 128, AT_TOT*4>>>(inputs);
        k_finalize<<<BB*SS, 192>>>(b_ih, b_hh, b1, b2,
                                   ln_mlp_w, ln_mlp_b, ln_slots_w, ln_slots_b,
                                   ln_in_w, ln_in_b,
                                   out, it == NUM_ITERS - 1 ? 1 : 0);
    }
}

// round 10
// speedup vs baseline: 1.5919x; 1.0446x over previous
#include <cuda_runtime.h>
#include <math.h>

#define BB 128
#define NN 4096
#define DD 64
#define SS 7
#define HH 128
#define NUM_ITERS 3
#define EPSV 1e-8f
#define LN_EPS 1e-5f
#define SCALE 0.125f   // 64^-0.5

typedef unsigned long long u64;

// persistent scratch (no allocation allowed)
__device__ float g_slots[BB*SS*DD];
__device__ float g_qt[BB*SS*DD];    // qw = ln_in_w ⊙ (q@Wk)  [b][s][64]
__device__ float g_qsc[BB*SS*2];    // {sw, sb} per (b,s)
__device__ float g_u[BB*SS*DD];     // G1 = sum_n (p*r) * x
__device__ float g_den[BB*SS];      // sum_n p
__device__ float g_c2[BB*SS];       // sum_n p*r*m
__device__ float g_M[DD*DD];        // scale * Wq^T @ Wk      [e][t]
__device__ float g_CT[DD*3*DD];     // (W_ih @ Wv)^T          [e][j]
__device__ float g_WHHT[DD*3*DD];   // W_hh^T                 [e][j]
__device__ float g_W1T[DD*HH];      // W1^T                   [e][j]
__device__ float g_W2T[HH*DD];      // W2^T                   [j][d]

// ---------------------------------------------------------------------------
__device__ __forceinline__ u64 pk(float lo, float hi){
    u64 r; asm("mov.b64 %0,{%1,%2};" : "=l"(r) : "f"(lo), "f"(hi)); return r;
}
__device__ __forceinline__ void upk(u64 v, float& lo, float& hi){
    asm("mov.b64 {%0,%1},%2;" : "=f"(lo), "=f"(hi) : "l"(v));
}
__device__ __forceinline__ void fma2(u64& d, u64 a, u64 b){
    asm("fma.rn.f32x2 %0,%1,%2,%0;" : "+l"(d) : "l"(a), "l"(b));
}
__device__ __forceinline__ void add2(u64& d, u64 a){
    asm("add.rn.f32x2 %0,%1,%0;" : "+l"(d) : "l"(a));
}
// fast exp: exp2 split with magic bias + degree-6 poly (rel err ~1e-7)
__device__ __forceinline__ float fexp(float x){
    float t = fmaxf(x * 1.4426950408889634f, -126.f);
    float z = __fadd_rn(t, 12582912.f);
    int n = __float_as_int(z) - 0x4B400000;
    float f = t - __fsub_rn(z, 12582912.f);
    float p =         1.5403530e-4f;
    p = fmaf(p, f,    1.3333558e-3f);
    p = fmaf(p, f,    9.6181291e-3f);
    p = fmaf(p, f,    5.5504109e-2f);
    p = fmaf(p, f,    2.4022651e-1f);
    p = fmaf(p, f,    6.9314718e-1f);
    p = fmaf(p, f,    1.0f);
    return p * __int_as_float((n + 127) << 23);
}
__device__ __forceinline__ float ftanh(float x){
    return 1.f - __fdividef(2.f, 1.f + __expf(2.f*x));
}

// ---------------------------------------------------------------------------
// blocks 0..15: M ; 16..63: CT (dot) ; 64..175: transposes WHHT/W1T/W2T
__global__ void k_precomp(const float* __restrict__ Wq,
                          const float* __restrict__ Wk,
                          const float* __restrict__ W_ih,
                          const float* __restrict__ Wv,
                          const float* __restrict__ W_hh,
                          const float* __restrict__ W1,
                          const float* __restrict__ W2) {
    int bi = blockIdx.x, t = threadIdx.x;
    if (bi < 16) {
        int o = bi*256 + t;
        int e = o >> 6, tc = o & 63;
        float acc = 0.f;
        #pragma unroll 8
        for (int d = 0; d < 64; d++)
            acc += Wq[d*64 + e] * Wk[d*64 + tc];
        g_M[e*64 + tc] = acc * SCALE;
    } else if (bi < 64) {
        int o = (bi-16)*256 + t;        // o = e*192 + j
        int e = o / 192, j = o - e*192;
        float acc = 0.f;
        #pragma unroll 8
        for (int h = 0; h < 64; h++)
            acc += W_ih[j*64 + h] * Wv[h*64 + e];
        g_CT[o] = acc;
    } else {
        int idx = (bi-64)*256 + t;
        if (idx < 12288) {
            int e = idx / 192, j = idx - e*192;
            g_WHHT[idx] = W_hh[j*64 + e];
        } else if (idx < 20480) {
            int o = idx - 12288;
            int e = o >> 7, j = o & 127;
            g_W1T[o] = W1[j*64 + e];
        } else {
            int o = idx - 20480;
            int j = o >> 6, d = o & 63;
            g_W2T[o] = W2[d*128 + j];
        }
    }
}

// ---------------------------------------------------------------------------
// init slots + initial q prep + zero accumulators (merged)
__global__ void k_q0(const float* __restrict__ noise,
                     const float* __restrict__ mu,
                     const float* __restrict__ logsig,
                     const float* __restrict__ lnw,
                     const float* __restrict__ lnb,
                     const float* __restrict__ w_in,
                     const float* __restrict__ b_in) {
    int b = blockIdx.x;
    int tid = threadIdx.x;
    int w = tid >> 5, lane = tid & 31;
    __shared__ float sl[SS*64];
    __shared__ float sn[SS*64];
    __shared__ float qtmp[SS*64];

    for (int i = tid; i < SS*64; i += 256) {
        int d = i & 63;
        float v = mu[d] + expf(logsig[d]) * noise[b*SS*64 + i];
        g_slots[b*SS*64 + i] = v;
        sl[i] = v;
        g_u[b*SS*64 + i] = 0.f;
    }
    if (tid < SS) { g_den[b*SS + tid] = 0.f; g_c2[b*SS + tid] = 0.f; }
    __syncthreads();

    if (w < SS) {
        float v0 = sl[w*64 + lane], v1 = sl[w*64 + lane+32];
        float sum = v0 + v1, sq = v0*v0 + v1*v1;
        #pragma unroll
        for (int o = 16; o; o >>= 1) {
            sum += __shfl_xor_sync(0xffffffffu, sum, o);
            sq  += __shfl_xor_sync(0xffffffffu, sq,  o);
        }
        float mean = sum * (1.f/64.f);
        float var  = sq  * (1.f/64.f) - mean*mean;
        float rstd = rsqrtf(var + LN_EPS);
        sn[w*64 + lane]    = (v0 - mean)*rstd*lnw[lane]    + lnb[lane];
        sn[w*64 + lane+32] = (v1 - mean)*rstd*lnw[lane+32] + lnb[lane+32];
    }
    __syncthreads();

    for (int i = tid; i < SS*64; i += 256) {
        int s = i >> 6, tc = i & 63;
        float acc = 0.f;
        #pragma unroll 8
        for (int e = 0; e < 64; e++)
            acc += sn[s*64 + e] * g_M[e*64 + tc];
        qtmp[i] = acc;
        g_qt[b*SS*64 + i] = acc * w_in[tc];
    }
    __syncthreads();
    if (tid < 14) {
        int s = tid >> 1;
        float acc = 0.f;
        if ((tid & 1) == 0) {
            for (int tc = 0; tc < 64; tc++) acc += qtmp[s*64+tc] * w_in[tc];
        } else {
            for (int tc = 0; tc < 64; tc++) acc += qtmp[s*64+tc] * b_in[tc];
        }
        g_qsc[b*SS*2 + tid] = acc;
    }
}

// ---------------------------------------------------------------------------
// Streaming pass: 256 threads, 128-token tile, warp owns 16 tokens,
// 2 lanes per token in phase A (k-halves, shfl-combined).
// smem floats: xs 8*1088 | prs 8*160 | qw 448 | qsc 16
#define AT_XS   0
#define AT_PRS  8704
#define AT_QW   9984
#define AT_QSC  10432
#define AT_TOT  10448

__global__ void __launch_bounds__(256) k_attn(const float* __restrict__ inputs) {
    extern __shared__ float smf[];
    int b = blockIdx.y, tile = blockIdx.x;
    int tid = threadIdx.x;
    int w = tid >> 5, lane = tid & 31;

    for (int i = tid; i < SS*64; i += 256) smf[AT_QW + i] = g_qt[b*SS*64 + i];
    if (tid < 14) smf[AT_QSC + tid] = g_qsc[b*14 + tid];

    // stage 128 tokens (coalesced): 2048 float4
    const float4* src4 = (const float4*)(inputs +
                         ((size_t)b*NN + (size_t)tile*128) * DD);
    float4* xs4 = (float4*)(smf + AT_XS);
    #pragma unroll
    for (int k = 0; k < 8; k++) {
        int idx = tid + 256*k;
        int token = idx >> 4, chunk = idx & 15;
        xs4[(token >> 4)*272 + (token & 15)*17 + chunk] = src4[idx];
    }
    __syncthreads();

    float4* xsw  = (float4*)(smf + AT_XS) + w*272;
    float*  prsw = smf + AT_PRS + w*160;

    // phase A: token = lane&15, k-half = lane>>4
    {
        int tl = lane & 15, half = lane >> 4;
        const ulonglong2* row = (const ulonglong2*)(xsw + tl*17 + half*8);
        const ulonglong2* qwu = (const ulonglong2*)(smf + AT_QW);
        u64 dot2[SS];
        #pragma unroll
        for (int s = 0; s < SS; s++) dot2[s] = 0;
        u64 sum2 = 0, sq2 = 0;
        #pragma unroll
        for (int k = 0; k < 8; k++) {
            ulonglong2 v = row[k];
            add2(sum2, v.x); add2(sum2, v.y);
            fma2(sq2, v.x, v.x); fma2(sq2, v.y, v.y);
            #pragma unroll
            for (int s = 0; s < SS; s++) {
                ulonglong2 q = qwu[s*16 + half*8 + k];
                fma2(dot2[s], v.x, q.x);
                fma2(dot2[s], v.y, q.y);
            }
        }
        float lo, hi;
        upk(sum2, lo, hi); float sum = lo + hi;
        upk(sq2,  lo, hi); float sq  = lo + hi;
        sum += __shfl_xor_sync(0xffffffffu, sum, 16);
        sq  += __shfl_xor_sync(0xffffffffu, sq,  16);

        float dot[SS];
        #pragma unroll
        for (int s = 0; s < SS; s++) {
            upk(dot2[s], lo, hi);
            dot[s] = lo + hi;
            dot[s] += __shfl_xor_sync(0xffffffffu, dot[s], 16);
        }

        float m = sum * (1.f/64.f);
        float vr = fmaf(sq, 1.f/64.f, -m*m) + LN_EPS;
        float r = rsqrtf(vr);
        float inv_r = vr * r;

        float lg[SS];
        #pragma unroll
        for (int s = 0; s < SS; s++) {
            float t1 = fmaf(-m, smf[AT_QSC + 2*s], dot[s]);
            lg[s] = fmaf(r, t1, smf[AT_QSC + 2*s + 1]);
        }
        float mx = lg[0];
        #pragma unroll
        for (int s = 1; s < SS; s++) mx = fmaxf(mx, lg[s]);
        float ex[SS], tot = 0.f;
        #pragma unroll
        for (int s = 0; s < SS; s++) { ex[s] = fexp(lg[s] - mx); tot += ex[s]; }
        float inv = __fdividef(1.f, tot);

        if (half == 0) {
            #pragma unroll
            for (int s = 0; s < SS; s++) {
                float p = fmaf(ex[s], inv, EPSV);
                prsw[tl*8 + s] = p * r;
            }
            prsw[tl*8 + 7] = inv_r;
            prsw[128 + tl] = m;
        }
    }
    __syncwarp();

    // den / c2 (lanes 0..13): p = pr*inv_r, c2 term = pr*m
    if (lane < 14) {
        int s7 = (lane < 7) ? lane : lane - 7;
        float val = 0.f;
        if (lane < 7) {
            #pragma unroll
            for (int t = 0; t < 16; t++) val += prsw[t*8 + s7] * prsw[t*8 + 7];
            atomicAdd(&g_den[b*SS + s7], val);
        } else {
            #pragma unroll
            for (int t = 0; t < 16; t++) val += prsw[t*8 + s7] * prsw[128 + t];
            atomicAdd(&g_c2[b*SS + s7], val);
        }
    }

    // phase B: warp-local outer product over its 16 tokens
    {
        int h = lane >> 4, e4 = lane & 15;
        u64 acca[SS], accb[SS];
        #pragma unroll
        for (int s = 0; s < SS; s++) { acca[s] = 0; accb[s] = 0; }
        #pragma unroll
        for (int j = 0; j < 8; j++) {
            int t = 2*j + h;
            ulonglong2 xv = *(const ulonglong2*)(xsw + t*17 + e4);
            float4 p0 = *(const float4*)(prsw + t*8);
            float4 p1 = *(const float4*)(prsw + t*8 + 4);
            u64 q0 = pk(p0.x, p0.x), q1 = pk(p0.y, p0.y);
            u64 q2 = pk(p0.z, p0.z), q3 = pk(p0.w, p0.w);
            u64 q4 = pk(p1.x, p1.x), q5 = pk(p1.y, p1.y);
            u64 q6 = pk(p1.z, p1.z);
            fma2(acca[0], xv.x, q0); fma2(accb[0], xv.y, q0);
            fma2(acca[1], xv.x, q1); fma2(accb[1], xv.y, q1);
            fma2(acca[2], xv.x, q2); fma2(accb[2], xv.y, q2);
            fma2(acca[3], xv.x, q3); fma2(accb[3], xv.y, q3);
            fma2(acca[4], xv.x, q4); fma2(accb[4], xv.y, q4);
            fma2(acca[5], xv.x, q5); fma2(accb[5], xv.y, q5);
            fma2(acca[6], xv.x, q6); fma2(accb[6], xv.y, q6);
        }
        float4* psumw = xsw;   // reuse own xs region
        #pragma unroll
        for (int s = 0; s < SS; s++) {
            u64 oa = __shfl_xor_sync(0xffffffffu, acca[s], 16);
            u64 ob = __shfl_xor_sync(0xffffffffu, accb[s], 16);
            add2(acca[s], oa); add2(accb[s], ob);
            if (h == 0) {
                float4 o;
                upk(acca[s], o.x, o.y);
                upk(accb[s], o.z, o.w);
                psumw[s*16 + e4] = o;
            }
        }
    }
    __syncthreads();

    if (tid < 112) {
        int s = tid >> 4, e4 = tid & 15;
        float4 acc = make_float4(0.f, 0.f, 0.f, 0.f);
        #pragma unroll
        for (int w2 = 0; w2 < 8; w2++) {
            float4 v = ((const float4*)(smf + AT_XS))[w2*272 + s*16 + e4];
            acc.x += v.x; acc.y += v.y; acc.z += v.z; acc.w += v.w;
        }
        float* up = g_u + (b*SS + s)*DD + e4*4;
        atomicAdd(up+0, acc.x); atomicAdd(up+1, acc.y);
        atomicAdd(up+2, acc.z); atomicAdd(up+3, acc.w);
    }
}

// ---------------------------------------------------------------------------
// finalize: one block per (batch, slot) = 896 blocks, 192 threads.
// split accumulators to break FMA chains; fast tanh.
__global__ void __launch_bounds__(192) k_finalize(
        const float* __restrict__ b_ih, const float* __restrict__ b_hh,
        const float* __restrict__ b1,  const float* __restrict__ b2,
        const float* __restrict__ ln_mlp_w, const float* __restrict__ ln_mlp_b,
        const float* __restrict__ ln_slots_w, const float* __restrict__ ln_slots_b,
        const float* __restrict__ ln_in_w, const float* __restrict__ ln_in_b,
        float* __restrict__ out, int last) {
    __shared__ float upd[64], prev[64], giv[192], ghv[192],
                     act[64], mln[64], h1[128], red[8];
    int bs = blockIdx.x;
    int tid = threadIdx.x;

    if (tid < 64) {
        float invden = __fdividef(1.f, g_den[bs]);
        upd[tid] = fmaf(ln_in_w[tid]*invden, g_u[bs*64 + tid] - g_c2[bs],
                        ln_in_b[tid]);
        prev[tid] = g_slots[bs*64 + tid];
    }
    __syncthreads();

    // gi = upd@C^T + b_ih ; gh = prev@W_hh^T + b_hh  (2 accs each)
    {
        float ai0 = b_ih[tid], ah0 = b_hh[tid];
        float ai1 = 0.f, ah1 = 0.f;
        #pragma unroll 16
        for (int e = 0; e < 64; e += 2) {
            ai0 = fmaf(upd[e],    g_CT[e*192 + tid],       ai0);
            ai1 = fmaf(upd[e+1],  g_CT[(e+1)*192 + tid],   ai1);
            ah0 = fmaf(prev[e],   g_WHHT[e*192 + tid],     ah0);
            ah1 = fmaf(prev[e+1], g_WHHT[(e+1)*192 + tid], ah1);
        }
        giv[tid] = ai0 + ai1; ghv[tid] = ah0 + ah1;
    }
    __syncthreads();

    // GRU + LN partials
    if (tid < 64) {
        float r = 1.f/(1.f + __expf(-(giv[tid]     + ghv[tid])));
        float z = 1.f/(1.f + __expf(-(giv[64+tid]  + ghv[64+tid])));
        float n = ftanh(fmaf(r, ghv[128+tid], giv[128+tid]));
        float v = (1.f - z)*n + z*prev[tid];
        act[tid] = v;
        float sum = v, sq = v*v;
        #pragma unroll
        for (int o = 16; o; o >>= 1) {
            sum += __shfl_xor_sync(0xffffffffu, sum, o);
            sq  += __shfl_xor_sync(0xffffffffu, sq,  o);
        }
        if ((tid & 31) == 0) { red[(tid>>5)*2] = sum; red[(tid>>5)*2+1] = sq; }
    }
    __syncthreads();

    if (tid < 64) {
        float sum = red[0] + red[2], sq = red[1] + red[3];
        float m = sum * (1.f/64.f);
        float var = sq * (1.f/64.f) - m*m;
        float r = rsqrtf(var + LN_EPS);
        mln[tid] = (act[tid] - m)*r*ln_mlp_w[tid] + ln_mlp_b[tid];
    }
    __syncthreads();

    if (tid < 128) {
        float a0 = b1[tid], a1 = 0.f;
        #pragma unroll 16
        for (int e = 0; e < 64; e += 2) {
            a0 = fmaf(mln[e],   g_W1T[e*128 + tid],     a0);
            a1 = fmaf(mln[e+1], g_W1T[(e+1)*128 + tid], a1);
        }
        h1[tid] = fmaxf(a0 + a1, 0.f);
    }
    __syncthreads();

    float res = 0.f;
    if (tid < 64) {
        float a0 = b2[tid], a1 = 0.f;
        #pragma unroll 16
        for (int j = 0; j < 128; j += 2) {
            a0 = fmaf(h1[j],   g_W2T[j*64 + tid],     a0);
            a1 = fmaf(h1[j+1], g_W2T[(j+1)*64 + tid], a1);
        }
        res = act[tid] + a0 + a1;
        g_slots[bs*64 + tid] = res;
        if (last) out[bs*64 + tid] = res;
    }
    if (last) return;
    __syncthreads();

    // next-iteration prep: LN(res) -> qt -> qw/sw/sb ; zero accumulators
    if (tid < 64) {
        float sum = res, sq = res*res;
        #pragma unroll
        for (int o = 16; o; o >>= 1) {
            sum += __shfl_xor_sync(0xffffffffu, sum, o);
            sq  += __shfl_xor_sync(0xffffffffu, sq,  o);
        }
        if ((tid & 31) == 0) { red[(tid>>5)*2] = sum; red[(tid>>5)*2+1] = sq; }
        g_u[bs*64 + tid] = 0.f;
    }
    if (tid == 0) { g_den[bs] = 0.f; g_c2[bs] = 0.f; }
    __syncthreads();

    if (tid < 64) {
        float sum = red[0] + red[2], sq = red[1] + red[3];
        float m = sum * (1.f/64.f);
        float var = sq * (1.f/64.f) - m*m;
        float r = rsqrtf(var + LN_EPS);
        mln[tid] = (res - m)*r*ln_slots_w[tid] + ln_slots_b[tid];   // reuse as sn
    }
    __syncthreads();

    if (tid < 64) {
        float a0 = 0.f, a1 = 0.f;
        #pragma unroll 16
        for (int e = 0; e < 64; e += 2) {
            a0 = fmaf(mln[e],   g_M[e*64 + tid],     a0);
            a1 = fmaf(mln[e+1], g_M[(e+1)*64 + tid], a1);
        }
        float acc = a0 + a1;
        g_qt[bs*64 + tid] = acc * ln_in_w[tid];
        float pa = acc * ln_in_w[tid];
        float pb = acc * ln_in_b[tid];
        #pragma unroll
        for (int o = 16; o; o >>= 1) {
            pa += __shfl_xor_sync(0xffffffffu, pa, o);
            pb += __shfl_xor_sync(0xffffffffu, pb, o);
        }
        if ((tid & 31) == 0) { red[(tid>>5)*2] = pa; red[(tid>>5)*2+1] = pb; }
    }
    __syncthreads();
    if (tid == 0) {
        g_qsc[bs*2 + 0] = red[0] + red[2];
        g_qsc[bs*2 + 1] = red[1] + red[3];
    }
}

// ---------------------------------------------------------------------------
extern "C" void kernel_launch(void* const* d_in, const int* in_sizes, int n_in,
                              void* d_out, int out_size) {
    const float* inputs     = (const float*)d_in[0];
    const float* noise      = (const float*)d_in[1];
    const float* ln_in_w    = (const float*)d_in[2];
    const float* ln_in_b    = (const float*)d_in[3];
    const float* ln_slots_w = (const float*)d_in[4];
    const float* ln_slots_b = (const float*)d_in[5];
    const float* ln_mlp_w   = (const float*)d_in[6];
    const float* ln_mlp_b   = (const float*)d_in[7];
    const float* mu         = (const float*)d_in[8];
    const float* logsig     = (const float*)d_in[9];
    const float* Wq         = (const float*)d_in[10];
    const float* Wk         = (const float*)d_in[11];
    const float* Wv         = (const float*)d_in[12];
    const float* W_ih       = (const float*)d_in[13];
    const float* W_hh       = (const float*)d_in[14];
    const float* b_ih       = (const float*)d_in[15];
    const float* b_hh       = (const float*)d_in[16];
    const float* W1         = (const float*)d_in[17];
    const float* b1         = (const float*)d_in[18];
    const float* W2         = (const float*)d_in[19];
    const float* b2         = (const float*)d_in[20];
    float* out = (float*)d_out;

    cudaFuncSetAttribute(k_attn, cudaFuncAttributeMaxDynamicSharedMemorySize,
                         AT_TOT*4);

    k_precomp<<<176, 256>>>(Wq, Wk, W_ih, Wv, W_hh, W1, W2);
    k_q0<<<BB, 256>>>(noise, mu, logsig, ln_slots_w, ln_slots_b,
                      ln_in_w, ln_in_b);
    for (int it = 0; it < NUM_ITERS; it++) {
        dim3 grid(NN/128, BB);
        k_attn<<<grid, 256, AT_TOT*4>>>(inputs);
        k_finalize<<<BB*SS, 192>>>(b_ih, b_hh, b1, b2,
                                   ln_mlp_w, ln_mlp_b, ln_slots_w, ln_slots_b,
                                   ln_in_w, ln_in_b,
                                   out, it == NUM_ITERS - 1 ? 1 : 0);
    }
}

// round 11
// speedup vs baseline: 1.6877x; 1.0602x over previous
#include <cuda_runtime.h>
#include <cuda_fp16.h>
#include <math.h>

#define BB 128
#define NN 4096
#define DD 64
#define SS 7
#define HH 128
#define NUM_ITERS 3
#define EPSV 1e-8f
#define LN_EPS 1e-5f
#define SCALE 0.125f   // 64^-0.5

typedef unsigned long long u64;

// persistent scratch (no allocation allowed)
__device__ float g_slots[BB*SS*DD];
__device__ float g_qt[BB*SS*DD];    // qw = ln_in_w ⊙ (q@Wk)  [b][s][64]
__device__ float g_qsc[BB*SS*2];    // {sw, sb} per (b,s)
__device__ float g_u[BB*SS*DD];     // G1 = sum_n (p*r) * x
__device__ float g_den[BB*SS];      // sum_n p
__device__ float g_c2[BB*SS];       // sum_n p*r*m
__device__ float g_M[DD*DD];        // scale * Wq^T @ Wk      [e][t]
__device__ float g_CT[DD*3*DD];     // (W_ih @ Wv)^T          [e][j]
__device__ float g_WHHT[DD*3*DD];   // W_hh^T                 [e][j]
__device__ float g_W1T[DD*HH];      // W1^T                   [e][j]
__device__ float g_W2T[HH*DD];      // W2^T                   [j][d]
__device__ __half g_xh[(size_t)BB*NN*DD];   // fp16 shadow of inputs (67MB)

// ---------------------------------------------------------------------------
__device__ __forceinline__ u64 pk(float lo, float hi){
    u64 r; asm("mov.b64 %0,{%1,%2};" : "=l"(r) : "f"(lo), "f"(hi)); return r;
}
__device__ __forceinline__ void upk(u64 v, float& lo, float& hi){
    asm("mov.b64 {%0,%1},%2;" : "=f"(lo), "=f"(hi) : "l"(v));
}
__device__ __forceinline__ void fma2(u64& d, u64 a, u64 b){
    asm("fma.rn.f32x2 %0,%1,%2,%0;" : "+l"(d) : "l"(a), "l"(b));
}
__device__ __forceinline__ void add2(u64& d, u64 a){
    asm("add.rn.f32x2 %0,%1,%0;" : "+l"(d) : "l"(a));
}
// fast exp: exp2 split with magic bias + degree-6 poly (rel err ~1e-7)
__device__ __forceinline__ float fexp(float x){
    float t = fmaxf(x * 1.4426950408889634f, -126.f);
    float z = __fadd_rn(t, 12582912.f);
    int n = __float_as_int(z) - 0x4B400000;
    float f = t - __fsub_rn(z, 12582912.f);
    float p =         1.5403530e-4f;
    p = fmaf(p, f,    1.3333558e-3f);
    p = fmaf(p, f,    9.6181291e-3f);
    p = fmaf(p, f,    5.5504109e-2f);
    p = fmaf(p, f,    2.4022651e-1f);
    p = fmaf(p, f,    6.9314718e-1f);
    p = fmaf(p, f,    1.0f);
    return p * __int_as_float((n + 127) << 23);
}
__device__ __forceinline__ float ftanh(float x){
    return 1.f - __fdividef(2.f, 1.f + __expf(2.f*x));
}

// ---------------------------------------------------------------------------
// blocks 0..15: M ; 16..63: CT (dot) ; 64..175: transposes WHHT/W1T/W2T
__global__ void k_precomp(const float* __restrict__ Wq,
                          const float* __restrict__ Wk,
                          const float* __restrict__ W_ih,
                          const float* __restrict__ Wv,
                          const float* __restrict__ W_hh,
                          const float* __restrict__ W1,
                          const float* __restrict__ W2) {
    int bi = blockIdx.x, t = threadIdx.x;
    if (bi < 16) {
        int o = bi*256 + t;
        int e = o >> 6, tc = o & 63;
        float acc = 0.f;
        #pragma unroll 8
        for (int d = 0; d < 64; d++)
            acc += Wq[d*64 + e] * Wk[d*64 + tc];
        g_M[e*64 + tc] = acc * SCALE;
    } else if (bi < 64) {
        int o = (bi-16)*256 + t;        // o = e*192 + j
        int e = o / 192, j = o - e*192;
        float acc = 0.f;
        #pragma unroll 8
        for (int h = 0; h < 64; h++)
            acc += W_ih[j*64 + h] * Wv[h*64 + e];
        g_CT[o] = acc;
    } else {
        int idx = (bi-64)*256 + t;
        if (idx < 12288) {
            int e = idx / 192, j = idx - e*192;
            g_WHHT[idx] = W_hh[j*64 + e];
        } else if (idx < 20480) {
            int o = idx - 12288;
            int e = o >> 7, j = o & 127;
            g_W1T[o] = W1[j*64 + e];
        } else {
            int o = idx - 20480;
            int j = o >> 6, d = o & 63;
            g_W2T[o] = W2[d*128 + j];
        }
    }
}

// ---------------------------------------------------------------------------
// init slots + initial q prep + zero accumulators (merged)
__global__ void k_q0(const float* __restrict__ noise,
                     const float* __restrict__ mu,
                     const float* __restrict__ logsig,
                     const float* __restrict__ lnw,
                     const float* __restrict__ lnb,
                     const float* __restrict__ w_in,
                     const float* __restrict__ b_in) {
    int b = blockIdx.x;
    int tid = threadIdx.x;
    int w = tid >> 5, lane = tid & 31;
    __shared__ float sl[SS*64];
    __shared__ float sn[SS*64];
    __shared__ float qtmp[SS*64];

    for (int i = tid; i < SS*64; i += 256) {
        int d = i & 63;
        float v = mu[d] + expf(logsig[d]) * noise[b*SS*64 + i];
        g_slots[b*SS*64 + i] = v;
        sl[i] = v;
        g_u[b*SS*64 + i] = 0.f;
    }
    if (tid < SS) { g_den[b*SS + tid] = 0.f; g_c2[b*SS + tid] = 0.f; }
    __syncthreads();

    if (w < SS) {
        float v0 = sl[w*64 + lane], v1 = sl[w*64 + lane+32];
        float sum = v0 + v1, sq = v0*v0 + v1*v1;
        #pragma unroll
        for (int o = 16; o; o >>= 1) {
            sum += __shfl_xor_sync(0xffffffffu, sum, o);
            sq  += __shfl_xor_sync(0xffffffffu, sq,  o);
        }
        float mean = sum * (1.f/64.f);
        float var  = sq  * (1.f/64.f) - mean*mean;
        float rstd = rsqrtf(var + LN_EPS);
        sn[w*64 + lane]    = (v0 - mean)*rstd*lnw[lane]    + lnb[lane];
        sn[w*64 + lane+32] = (v1 - mean)*rstd*lnw[lane+32] + lnb[lane+32];
    }
    __syncthreads();

    for (int i = tid; i < SS*64; i += 256) {
        int s = i >> 6, tc = i & 63;
        float acc = 0.f;
        #pragma unroll 8
        for (int e = 0; e < 64; e++)
            acc += sn[s*64 + e] * g_M[e*64 + tc];
        qtmp[i] = acc;
        g_qt[b*SS*64 + i] = acc * w_in[tc];
    }
    __syncthreads();
    if (tid < 14) {
        int s = tid >> 1;
        float acc = 0.f;
        if ((tid & 1) == 0) {
            for (int tc = 0; tc < 64; tc++) acc += qtmp[s*64+tc] * w_in[tc];
        } else {
            for (int tc = 0; tc < 64; tc++) acc += qtmp[s*64+tc] * b_in[tc];
        }
        g_qsc[b*SS*2 + tid] = acc;
    }
}

// ---------------------------------------------------------------------------
// Streaming pass: 256 threads, 128-token tile, warp owns 16 tokens,
// 2 lanes per token in phase A (k-halves, shfl-combined).
// FIRST=1: read fp32 inputs, also emit fp16 shadow. FIRST=0: read fp16 shadow.
// smem floats: xs 8*1088 | prs 8*160 | qw 448 | qsc 16
#define AT_XS   0
#define AT_PRS  8704
#define AT_QW   9984
#define AT_QSC  10432
#define AT_TOT  10448

template<int FIRST>
__global__ void __launch_bounds__(256) k_attn(const float* __restrict__ inputs) {
    extern __shared__ float smf[];
    int b = blockIdx.y, tile = blockIdx.x;
    int tid = threadIdx.x;
    int w = tid >> 5, lane = tid & 31;

    for (int i = tid; i < SS*64; i += 256) smf[AT_QW + i] = g_qt[b*SS*64 + i];
    if (tid < 14) smf[AT_QSC + tid] = g_qsc[b*14 + tid];

    float4* xs4 = (float4*)(smf + AT_XS);
    size_t base = ((size_t)b*NN + (size_t)tile*128) * DD;

    if (FIRST) {
        // stage fp32 + emit fp16 shadow
        const float4* src4 = (const float4*)(inputs + base);
        __half2* dsth = (__half2*)(g_xh + base);
        #pragma unroll
        for (int k = 0; k < 8; k++) {
            int idx = tid + 256*k;
            float4 v = src4[idx];
            int token = idx >> 4, chunk = idx & 15;
            xs4[(token >> 4)*272 + (token & 15)*17 + chunk] = v;
            union { uint2 u; __half2 h[2]; } pk2;
            pk2.h[0] = __floats2half2_rn(v.x, v.y);
            pk2.h[1] = __floats2half2_rn(v.z, v.w);
            *(uint2*)(dsth + idx*2) = pk2.u;
        }
    } else {
        // stage from fp16 shadow (half DRAM traffic, L2-resident)
        const uint4* srch = (const uint4*)(g_xh + base);
        #pragma unroll
        for (int it = 0; it < 4; it++) {
            int idx = tid + 256*it;          // uint4 = 8 halves = 2 float4 chunks
            uint4 v = srch[idx];
            float2 f0 = __half22float2(*(__half2*)&v.x);
            float2 f1 = __half22float2(*(__half2*)&v.y);
            float2 f2 = __half22float2(*(__half2*)&v.z);
            float2 f3 = __half22float2(*(__half2*)&v.w);
            int c0 = idx*2;
            int token = c0 >> 4, ch = c0 & 15;
            float4* p = xs4 + (token >> 4)*272 + (token & 15)*17 + ch;
            p[0] = make_float4(f0.x, f0.y, f1.x, f1.y);
            p[1] = make_float4(f2.x, f2.y, f3.x, f3.y);
        }
    }
    __syncthreads();

    float4* xsw  = (float4*)(smf + AT_XS) + w*272;
    float*  prsw = smf + AT_PRS + w*160;

    // phase A: token = lane&15, k-half = lane>>4
    {
        int tl = lane & 15, half = lane >> 4;
        const ulonglong2* row = (const ulonglong2*)(xsw + tl*17 + half*8);
        const ulonglong2* qwu = (const ulonglong2*)(smf + AT_QW);
        u64 dot2[SS];
        #pragma unroll
        for (int s = 0; s < SS; s++) dot2[s] = 0;
        u64 sum2 = 0, sq2 = 0;
        #pragma unroll
        for (int k = 0; k < 8; k++) {
            ulonglong2 v = row[k];
            add2(sum2, v.x); add2(sum2, v.y);
            fma2(sq2, v.x, v.x); fma2(sq2, v.y, v.y);
            #pragma unroll
            for (int s = 0; s < SS; s++) {
                ulonglong2 q = qwu[s*16 + half*8 + k];
                fma2(dot2[s], v.x, q.x);
                fma2(dot2[s], v.y, q.y);
            }
        }
        float lo, hi;
        upk(sum2, lo, hi); float sum = lo + hi;
        upk(sq2,  lo, hi); float sq  = lo + hi;
        sum += __shfl_xor_sync(0xffffffffu, sum, 16);
        sq  += __shfl_xor_sync(0xffffffffu, sq,  16);

        float dot[SS];
        #pragma unroll
        for (int s = 0; s < SS; s++) {
            upk(dot2[s], lo, hi);
            dot[s] = lo + hi;
            dot[s] += __shfl_xor_sync(0xffffffffu, dot[s], 16);
        }

        float m = sum * (1.f/64.f);
        float vr = fmaf(sq, 1.f/64.f, -m*m) + LN_EPS;
        float r = rsqrtf(vr);
        float inv_r = vr * r;

        float lg[SS];
        #pragma unroll
        for (int s = 0; s < SS; s++) {
            float t1 = fmaf(-m, smf[AT_QSC + 2*s], dot[s]);
            lg[s] = fmaf(r, t1, smf[AT_QSC + 2*s + 1]);
        }
        float mx = lg[0];
        #pragma unroll
        for (int s = 1; s < SS; s++) mx = fmaxf(mx, lg[s]);
        float ex[SS], tot = 0.f;
        #pragma unroll
        for (int s = 0; s < SS; s++) { ex[s] = fexp(lg[s] - mx); tot += ex[s]; }
        float inv = __fdividef(1.f, tot);

        if (half == 0) {
            #pragma unroll
            for (int s = 0; s < SS; s++) {
                float p = fmaf(ex[s], inv, EPSV);
                prsw[tl*8 + s] = p * r;
            }
            prsw[tl*8 + 7] = inv_r;
            prsw[128 + tl] = m;
        }
    }
    __syncwarp();

    // den / c2 (lanes 0..13): p = pr*inv_r, c2 term = pr*m
    if (lane < 14) {
        int s7 = (lane < 7) ? lane : lane - 7;
        float val = 0.f;
        if (lane < 7) {
            #pragma unroll
            for (int t = 0; t < 16; t++) val += prsw[t*8 + s7] * prsw[t*8 + 7];
            atomicAdd(&g_den[b*SS + s7], val);
        } else {
            #pragma unroll
            for (int t = 0; t < 16; t++) val += prsw[t*8 + s7] * prsw[128 + t];
            atomicAdd(&g_c2[b*SS + s7], val);
        }
    }

    // phase B: warp-local outer product over its 16 tokens
    {
        int h = lane >> 4, e4 = lane & 15;
        u64 acca[SS], accb[SS];
        #pragma unroll
        for (int s = 0; s < SS; s++) { acca[s] = 0; accb[s] = 0; }
        #pragma unroll
        for (int j = 0; j < 8; j++) {
            int t = 2*j + h;
            ulonglong2 xv = *(const ulonglong2*)(xsw + t*17 + e4);
            float4 p0 = *(const float4*)(prsw + t*8);
            float4 p1 = *(const float4*)(prsw + t*8 + 4);
            u64 q0 = pk(p0.x, p0.x), q1 = pk(p0.y, p0.y);
            u64 q2 = pk(p0.z, p0.z), q3 = pk(p0.w, p0.w);
            u64 q4 = pk(p1.x, p1.x), q5 = pk(p1.y, p1.y);
            u64 q6 = pk(p1.z, p1.z);
            fma2(acca[0], xv.x, q0); fma2(accb[0], xv.y, q0);
            fma2(acca[1], xv.x, q1); fma2(accb[1], xv.y, q1);
            fma2(acca[2], xv.x, q2); fma2(accb[2], xv.y, q2);
            fma2(acca[3], xv.x, q3); fma2(accb[3], xv.y, q3);
            fma2(acca[4], xv.x, q4); fma2(accb[4], xv.y, q4);
            fma2(acca[5], xv.x, q5); fma2(accb[5], xv.y, q5);
            fma2(acca[6], xv.x, q6); fma2(accb[6], xv.y, q6);
        }
        float4* psumw = xsw;   // reuse own xs region
        #pragma unroll
        for (int s = 0; s < SS; s++) {
            u64 oa = __shfl_xor_sync(0xffffffffu, acca[s], 16);
            u64 ob = __shfl_xor_sync(0xffffffffu, accb[s], 16);
            add2(acca[s], oa); add2(accb[s], ob);
            if (h == 0) {
                float4 o;
                upk(acca[s], o.x, o.y);
                upk(accb[s], o.z, o.w);
                psumw[s*16 + e4] = o;
            }
        }
    }
    __syncthreads();

    if (tid < 112) {
        int s = tid >> 4, e4 = tid & 15;
        float4 acc = make_float4(0.f, 0.f, 0.f, 0.f);
        #pragma unroll
        for (int w2 = 0; w2 < 8; w2++) {
            float4 v = ((const float4*)(smf + AT_XS))[w2*272 + s*16 + e4];
            acc.x += v.x; acc.y += v.y; acc.z += v.z; acc.w += v.w;
        }
        float* up = g_u + (b*SS + s)*DD + e4*4;
        atomicAdd(up+0, acc.x); atomicAdd(up+1, acc.y);
        atomicAdd(up+2, acc.z); atomicAdd(up+3, acc.w);
    }
}

// ---------------------------------------------------------------------------
// finalize: one block per (batch, slot) = 896 blocks, 192 threads.
__global__ void __launch_bounds__(192) k_finalize(
        const float* __restrict__ b_ih, const float* __restrict__ b_hh,
        const float* __restrict__ b1,  const float* __restrict__ b2,
        const float* __restrict__ ln_mlp_w, const float* __restrict__ ln_mlp_b,
        const float* __restrict__ ln_slots_w, const float* __restrict__ ln_slots_b,
        const float* __restrict__ ln_in_w, const float* __restrict__ ln_in_b,
        float* __restrict__ out, int last) {
    __shared__ float upd[64], prev[64], giv[192], ghv[192],
                     act[64], mln[64], h1[128], red[8];
    int bs = blockIdx.x;
    int tid = threadIdx.x;

    if (tid < 64) {
        float invden = __fdividef(1.f, g_den[bs]);
        upd[tid] = fmaf(ln_in_w[tid]*invden, g_u[bs*64 + tid] - g_c2[bs],
                        ln_in_b[tid]);
        prev[tid] = g_slots[bs*64 + tid];
    }
    __syncthreads();

    // gi = upd@C^T + b_ih ; gh = prev@W_hh^T + b_hh  (2 accs each)
    {
        float ai0 = b_ih[tid], ah0 = b_hh[tid];
        float ai1 = 0.f, ah1 = 0.f;
        #pragma unroll 16
        for (int e = 0; e < 64; e += 2) {
            ai0 = fmaf(upd[e],    g_CT[e*192 + tid],       ai0);
            ai1 = fmaf(upd[e+1],  g_CT[(e+1)*192 + tid],   ai1);
            ah0 = fmaf(prev[e],   g_WHHT[e*192 + tid],     ah0);
            ah1 = fmaf(prev[e+1], g_WHHT[(e+1)*192 + tid], ah1);
        }
        giv[tid] = ai0 + ai1; ghv[tid] = ah0 + ah1;
    }
    __syncthreads();

    // GRU + LN partials
    if (tid < 64) {
        float r = 1.f/(1.f + __expf(-(giv[tid]     + ghv[tid])));
        float z = 1.f/(1.f + __expf(-(giv[64+tid]  + ghv[64+tid])));
        float n = ftanh(fmaf(r, ghv[128+tid], giv[128+tid]));
        float v = (1.f - z)*n + z*prev[tid];
        act[tid] = v;
        float sum = v, sq = v*v;
        #pragma unroll
        for (int o = 16; o; o >>= 1) {
            sum += __shfl_xor_sync(0xffffffffu, sum, o);
            sq  += __shfl_xor_sync(0xffffffffu, sq,  o);
        }
        if ((tid & 31) == 0) { red[(tid>>5)*2] = sum; red[(tid>>5)*2+1] = sq; }
    }
    __syncthreads();

    if (tid < 64) {
        float sum = red[0] + red[2], sq = red[1] + red[3];
        float m = sum * (1.f/64.f);
        float var = sq * (1.f/64.f) - m*m;
        float r = rsqrtf(var + LN_EPS);
        mln[tid] = (act[tid] - m)*r*ln_mlp_w[tid] + ln_mlp_b[tid];
    }
    __syncthreads();

    if (tid < 128) {
        float a0 = b1[tid], a1 = 0.f;
        #pragma unroll 16
        for (int e = 0; e < 64; e += 2) {
            a0 = fmaf(mln[e],   g_W1T[e*128 + tid],     a0);
            a1 = fmaf(mln[e+1], g_W1T[(e+1)*128 + tid], a1);
        }
        h1[tid] = fmaxf(a0 + a1, 0.f);
    }
    __syncthreads();

    float res = 0.f;
    if (tid < 64) {
        float a0 = b2[tid], a1 = 0.f, a2 = 0.f, a3 = 0.f;
        #pragma unroll 8
        for (int j = 0; j < 128; j += 4) {
            a0 = fmaf(h1[j],   g_W2T[j*64 + tid],     a0);
            a1 = fmaf(h1[j+1], g_W2T[(j+1)*64 + tid], a1);
            a2 = fmaf(h1[j+2], g_W2T[(j+2)*64 + tid], a2);
            a3 = fmaf(h1[j+3], g_W2T[(j+3)*64 + tid], a3);
        }
        res = act[tid] + (a0 + a1) + (a2 + a3);
        g_slots[bs*64 + tid] = res;
        if (last) out[bs*64 + tid] = res;
    }
    if (last) return;
    __syncthreads();

    // next-iteration prep: LN(res) -> qt -> qw/sw/sb ; zero accumulators
    if (tid < 64) {
        float sum = res, sq = res*res;
        #pragma unroll
        for (int o = 16; o; o >>= 1) {
            sum += __shfl_xor_sync(0xffffffffu, sum, o);
            sq  += __shfl_xor_sync(0xffffffffu, sq,  o);
        }
        if ((tid & 31) == 0) { red[(tid>>5)*2] = sum; red[(tid>>5)*2+1] = sq; }
        g_u[bs*64 + tid] = 0.f;
    }
    if (tid == 0) { g_den[bs] = 0.f; g_c2[bs] = 0.f; }
    __syncthreads();

    if (tid < 64) {
        float sum = red[0] + red[2], sq = red[1] + red[3];
        float m = sum * (1.f/64.f);
        float var = sq * (1.f/64.f) - m*m;
        float r = rsqrtf(var + LN_EPS);
        mln[tid] = (res - m)*r*ln_slots_w[tid] + ln_slots_b[tid];   // reuse as sn
    }
    __syncthreads();

    if (tid < 64) {
        float a0 = 0.f, a1 = 0.f;
        #pragma unroll 16
        for (int e = 0; e < 64; e += 2) {
            a0 = fmaf(mln[e],   g_M[e*64 + tid],     a0);
            a1 = fmaf(mln[e+1], g_M[(e+1)*64 + tid], a1);
        }
        float acc = a0 + a1;
        g_qt[bs*64 + tid] = acc * ln_in_w[tid];
        float pa = acc * ln_in_w[tid];
        float pb = acc * ln_in_b[tid];
        #pragma unroll
        for (int o = 16; o; o >>= 1) {
            pa += __shfl_xor_sync(0xffffffffu, pa, o);
            pb += __shfl_xor_sync(0xffffffffu, pb, o);
        }
        if ((tid & 31) == 0) { red[(tid>>5)*2] = pa; red[(tid>>5)*2+1] = pb; }
    }
    __syncthreads();
    if (tid == 0) {
        g_qsc[bs*2 + 0] = red[0] + red[2];
        g_qsc[bs*2 + 1] = red[1] + red[3];
    }
}

// ---------------------------------------------------------------------------
extern "C" void kernel_launch(void* const* d_in, const int* in_sizes, int n_in,
                              void* d_out, int out_size) {
    const float* inputs     = (const float*)d_in[0];
    const float* noise      = (const float*)d_in[1];
    const float* ln_in_w    = (const float*)d_in[2];
    const float* ln_in_b    = (const float*)d_in[3];
    const float* ln_slots_w = (const float*)d_in[4];
    const float* ln_slots_b = (const float*)d_in[5];
    const float* ln_mlp_w   = (const float*)d_in[6];
    const float* ln_mlp_b   = (const float*)d_in[7];
    const float* mu         = (const float*)d_in[8];
    const float* logsig     = (const float*)d_in[9];
    const float* Wq         = (const float*)d_in[10];
    const float* Wk         = (const float*)d_in[11];
    const float* Wv         = (const float*)d_in[12];
    const float* W_ih       = (const float*)d_in[13];
    const float* W_hh       = (const float*)d_in[14];
    const float* b_ih       = (const float*)d_in[15];
    const float* b_hh       = (const float*)d_in[16];
    const float* W1         = (const float*)d_in[17];
    const float* b1         = (const float*)d_in[18];
    const float* W2         = (const float*)d_in[19];
    const float* b2         = (const float*)d_in[20];
    float* out = (float*)d_out;

    cudaFuncSetAttribute(k_attn<1>, cudaFuncAttributeMaxDynamicSharedMemorySize,
                         AT_TOT*4);
    cudaFuncSetAttribute(k_attn<0>, cudaFuncAttributeMaxDynamicSharedMemorySize,
                         AT_TOT*4);

    k_precomp<<<176, 256>>>(Wq, Wk, W_ih, Wv, W_hh, W1, W2);
    k_q0<<<BB, 256>>>(noise, mu, logsig, ln_slots_w, ln_slots_b,
                      ln_in_w, ln_in_b);
    dim3 grid(NN/128, BB);
    for (int it = 0; it < NUM_ITERS; it++) {
        if (it == 0) k_attn<1><<<grid, 256, AT_TOT*4>>>(inputs);
        else         k_attn<0><<<grid, 256, AT_TOT*4>>>(inputs);
        k_finalize<<<BB*SS, 192>>>(b_ih, b_hh, b1, b2,
                                   ln_mlp_w, ln_mlp_b, ln_slots_w, ln_slots_b,
                                   ln_in_w, ln_in_b,
                                   out, it == NUM_ITERS - 1 ? 1 : 0);
    }
}

// round 12
// speedup vs baseline: 1.7208x; 1.0196x over previous
#include <cuda_runtime.h>
#include <cuda_fp16.h>
#include <math.h>

#define BB 128
#define NN 4096
#define DD 64
#define SS 7
#define HH 128
#define NUM_ITERS 3
#define EPSV 1e-8f
#define LN_EPS 1e-5f
#define SCALE 0.125f   // 64^-0.5

typedef unsigned long long u64;

#define PDL_TRIGGER() asm volatile("griddepcontrol.launch_dependents;")
#define PDL_WAIT()    asm volatile("griddepcontrol.wait;" ::: "memory")

// persistent scratch (no allocation allowed)
__device__ float g_slots[BB*SS*DD];
__device__ float g_qt[BB*SS*DD];    // qw = ln_in_w ⊙ (q@Wk)  [b][s][64]
__device__ float g_qsc[BB*SS*2];    // {sw, sb} per (b,s)
__device__ float g_u[BB*SS*DD];     // G1 = sum_n (p*r) * x
__device__ float g_den[BB*SS];      // sum_n p
__device__ float g_c2[BB*SS];       // sum_n p*r*m
__device__ float g_M[DD*DD];        // scale * Wq^T @ Wk      [e][t]
__device__ float g_CT[DD*3*DD];     // (W_ih @ Wv)^T          [e][j]
__device__ float g_WHHT[DD*3*DD];   // W_hh^T                 [e][j]
__device__ float g_W1T[DD*HH];      // W1^T                   [e][j]
__device__ float g_W2T[HH*DD];      // W2^T                   [j][d]
__device__ __half g_xh[(size_t)BB*NN*DD];   // fp16 shadow of inputs (67MB)

// ---------------------------------------------------------------------------
__device__ __forceinline__ u64 pk(float lo, float hi){
    u64 r; asm("mov.b64 %0,{%1,%2};" : "=l"(r) : "f"(lo), "f"(hi)); return r;
}
__device__ __forceinline__ void upk(u64 v, float& lo, float& hi){
    asm("mov.b64 {%0,%1},%2;" : "=f"(lo), "=f"(hi) : "l"(v));
}
__device__ __forceinline__ void fma2(u64& d, u64 a, u64 b){
    asm("fma.rn.f32x2 %0,%1,%2,%0;" : "+l"(d) : "l"(a), "l"(b));
}
__device__ __forceinline__ void add2(u64& d, u64 a){
    asm("add.rn.f32x2 %0,%1,%0;" : "+l"(d) : "l"(a));
}
// fast exp: exp2 split with magic bias + degree-6 poly (rel err ~1e-7)
__device__ __forceinline__ float fexp(float x){
    float t = fmaxf(x * 1.4426950408889634f, -126.f);
    float z = __fadd_rn(t, 12582912.f);
    int n = __float_as_int(z) - 0x4B400000;
    float f = t - __fsub_rn(z, 12582912.f);
    float p =         1.5403530e-4f;
    p = fmaf(p, f,    1.3333558e-3f);
    p = fmaf(p, f,    9.6181291e-3f);
    p = fmaf(p, f,    5.5504109e-2f);
    p = fmaf(p, f,    2.4022651e-1f);
    p = fmaf(p, f,    6.9314718e-1f);
    p = fmaf(p, f,    1.0f);
    return p * __int_as_float((n + 127) << 23);
}
__device__ __forceinline__ float ftanh(float x){
    return 1.f - __fdividef(2.f, 1.f + __expf(2.f*x));
}

// ---------------------------------------------------------------------------
// blocks 0..15: M ; 16..63: CT (dot) ; 64..175: transposes WHHT/W1T/W2T
__global__ void k_precomp(const float* __restrict__ Wq,
                          const float* __restrict__ Wk,
                          const float* __restrict__ W_ih,
                          const float* __restrict__ Wv,
                          const float* __restrict__ W_hh,
                          const float* __restrict__ W1,
                          const float* __restrict__ W2) {
    int bi = blockIdx.x, t = threadIdx.x;
    if (bi < 16) {
        int o = bi*256 + t;
        int e = o >> 6, tc = o & 63;
        float acc = 0.f;
        #pragma unroll 8
        for (int d = 0; d < 64; d++)
            acc += Wq[d*64 + e] * Wk[d*64 + tc];
        g_M[e*64 + tc] = acc * SCALE;
    } else if (bi < 64) {
        int o = (bi-16)*256 + t;        // o = e*192 + j
        int e = o / 192, j = o - e*192;
        float acc = 0.f;
        #pragma unroll 8
        for (int h = 0; h < 64; h++)
            acc += W_ih[j*64 + h] * Wv[h*64 + e];
        g_CT[o] = acc;
    } else {
        int idx = (bi-64)*256 + t;
        if (idx < 12288) {
            int e = idx / 192, j = idx - e*192;
            g_WHHT[idx] = W_hh[j*64 + e];
        } else if (idx < 20480) {
            int o = idx - 12288;
            int e = o >> 7, j = o & 127;
            g_W1T[o] = W1[j*64 + e];
        } else {
            int o = idx - 20480;
            int j = o >> 6, d = o & 63;
            g_W2T[o] = W2[d*128 + j];
        }
    }
}

// ---------------------------------------------------------------------------
// init slots + initial q prep + zero accumulators (merged). PDL secondary.
__global__ void k_q0(const float* __restrict__ noise,
                     const float* __restrict__ mu,
                     const float* __restrict__ logsig,
                     const float* __restrict__ lnw,
                     const float* __restrict__ lnb,
                     const float* __restrict__ w_in,
                     const float* __restrict__ b_in) {
    int b = blockIdx.x;
    int tid = threadIdx.x;
    int w = tid >> 5, lane = tid & 31;
    __shared__ float sl[SS*64];
    __shared__ float sn[SS*64];
    __shared__ float qtmp[SS*64];

    PDL_TRIGGER();   // attn0's prologue (x staging) is independent of q0

    for (int i = tid; i < SS*64; i += 256) {
        int d = i & 63;
        float v = mu[d] + expf(logsig[d]) * noise[b*SS*64 + i];
        g_slots[b*SS*64 + i] = v;
        sl[i] = v;
        g_u[b*SS*64 + i] = 0.f;
    }
    if (tid < SS) { g_den[b*SS + tid] = 0.f; g_c2[b*SS + tid] = 0.f; }
    __syncthreads();

    if (w < SS) {
        float v0 = sl[w*64 + lane], v1 = sl[w*64 + lane+32];
        float sum = v0 + v1, sq = v0*v0 + v1*v1;
        #pragma unroll
        for (int o = 16; o; o >>= 1) {
            sum += __shfl_xor_sync(0xffffffffu, sum, o);
            sq  += __shfl_xor_sync(0xffffffffu, sq,  o);
        }
        float mean = sum * (1.f/64.f);
        float var  = sq  * (1.f/64.f) - mean*mean;
        float rstd = rsqrtf(var + LN_EPS);
        sn[w*64 + lane]    = (v0 - mean)*rstd*lnw[lane]    + lnb[lane];
        sn[w*64 + lane+32] = (v1 - mean)*rstd*lnw[lane+32] + lnb[lane+32];
    }
    PDL_WAIT();      // need g_M from k_precomp below
    __syncthreads();

    for (int i = tid; i < SS*64; i += 256) {
        int s = i >> 6, tc = i & 63;
        float acc = 0.f;
        #pragma unroll 8
        for (int e = 0; e < 64; e++)
            acc += sn[s*64 + e] * g_M[e*64 + tc];
        qtmp[i] = acc;
        g_qt[b*SS*64 + i] = acc * w_in[tc];
    }
    __syncthreads();
    if (tid < 14) {
        int s = tid >> 1;
        float acc = 0.f;
        if ((tid & 1) == 0) {
            for (int tc = 0; tc < 64; tc++) acc += qtmp[s*64+tc] * w_in[tc];
        } else {
            for (int tc = 0; tc < 64; tc++) acc += qtmp[s*64+tc] * b_in[tc];
        }
        g_qsc[b*SS*2 + tid] = acc;
    }
}

// ---------------------------------------------------------------------------
// Streaming pass: 256 threads, 128-token tile, warp owns 16 tokens,
// 2 lanes per token in phase A (k-halves, shfl-combined).
// FIRST=1: read fp32 inputs + emit fp16 shadow. FIRST=0: read fp16 shadow.
// PDL: stage x (independent) -> wait -> read qt/qsc.
#define AT_XS   0
#define AT_PRS  8704
#define AT_QW   9984
#define AT_QSC  10432
#define AT_TOT  10448

template<int FIRST>
__global__ void __launch_bounds__(256) k_attn(const float* __restrict__ inputs) {
    extern __shared__ float smf[];
    int b = blockIdx.y, tile = blockIdx.x;
    int tid = threadIdx.x;
    int w = tid >> 5, lane = tid & 31;

    PDL_TRIGGER();   // successor finalize's prologue (weight prefetch) is independent

    float4* xs4 = (float4*)(smf + AT_XS);
    size_t base = ((size_t)b*NN + (size_t)tile*128) * DD;

    if (FIRST) {
        // stage fp32 + emit fp16 shadow
        const float4* src4 = (const float4*)(inputs + base);
        __half2* dsth = (__half2*)(g_xh + base);
        #pragma unroll
        for (int k = 0; k < 8; k++) {
            int idx = tid + 256*k;
            float4 v = src4[idx];
            int token = idx >> 4, chunk = idx & 15;
            xs4[(token >> 4)*272 + (token & 15)*17 + chunk] = v;
            union { uint2 u; __half2 h[2]; } pk2;
            pk2.h[0] = __floats2half2_rn(v.x, v.y);
            pk2.h[1] = __floats2half2_rn(v.z, v.w);
            *(uint2*)(dsth + idx*2) = pk2.u;
        }
    } else {
        // stage from fp16 shadow (half DRAM traffic, L2-resident)
        const uint4* srch = (const uint4*)(g_xh + base);
        #pragma unroll
        for (int it = 0; it < 4; it++) {
            int idx = tid + 256*it;          // uint4 = 8 halves = 2 float4 chunks
            uint4 v = srch[idx];
            float2 f0 = __half22float2(*(__half2*)&v.x);
            float2 f1 = __half22float2(*(__half2*)&v.y);
            float2 f2 = __half22float2(*(__half2*)&v.z);
            float2 f3 = __half22float2(*(__half2*)&v.w);
            int c0 = idx*2;
            int token = c0 >> 4, ch = c0 & 15;
            float4* p = xs4 + (token >> 4)*272 + (token & 15)*17 + ch;
            p[0] = make_float4(f0.x, f0.y, f1.x, f1.y);
            p[1] = make_float4(f2.x, f2.y, f3.x, f3.y);
        }
    }

    PDL_WAIT();      // g_qt/g_qsc come from the predecessor (q0 or finalize)

    for (int i = tid; i < SS*64; i += 256) smf[AT_QW + i] = g_qt[b*SS*64 + i];
    if (tid < 14) smf[AT_QSC + tid] = g_qsc[b*14 + tid];
    __syncthreads();

    float4* xsw  = (float4*)(smf + AT_XS) + w*272;
    float*  prsw = smf + AT_PRS + w*160;

    // phase A: token = lane&15, k-half = lane>>4
    {
        int tl = lane & 15, half = lane >> 4;
        const ulonglong2* row = (const ulonglong2*)(xsw + tl*17 + half*8);
        const ulonglong2* qwu = (const ulonglong2*)(smf + AT_QW);
        u64 dot2[SS];
        #pragma unroll
        for (int s = 0; s < SS; s++) dot2[s] = 0;
        u64 sum2 = 0, sq2 = 0;
        #pragma unroll
        for (int k = 0; k < 8; k++) {
            ulonglong2 v = row[k];
            add2(sum2, v.x); add2(sum2, v.y);
            fma2(sq2, v.x, v.x); fma2(sq2, v.y, v.y);
            #pragma unroll
            for (int s = 0; s < SS; s++) {
                ulonglong2 q = qwu[s*16 + half*8 + k];
                fma2(dot2[s], v.x, q.x);
                fma2(dot2[s], v.y, q.y);
            }
        }
        float lo, hi;
        upk(sum2, lo, hi); float sum = lo + hi;
        upk(sq2,  lo, hi); float sq  = lo + hi;
        sum += __shfl_xor_sync(0xffffffffu, sum, 16);
        sq  += __shfl_xor_sync(0xffffffffu, sq,  16);

        float dot[SS];
        #pragma unroll
        for (int s = 0; s < SS; s++) {
            upk(dot2[s], lo, hi);
            dot[s] = lo + hi;
            dot[s] += __shfl_xor_sync(0xffffffffu, dot[s], 16);
        }

        float m = sum * (1.f/64.f);
        float vr = fmaf(sq, 1.f/64.f, -m*m) + LN_EPS;
        float r = rsqrtf(vr);
        float inv_r = vr * r;

        float lg[SS];
        #pragma unroll
        for (int s = 0; s < SS; s++) {
            float t1 = fmaf(-m, smf[AT_QSC + 2*s], dot[s]);
            lg[s] = fmaf(r, t1, smf[AT_QSC + 2*s + 1]);
        }
        float mx = lg[0];
        #pragma unroll
        for (int s = 1; s < SS; s++) mx = fmaxf(mx, lg[s]);
        float ex[SS], tot = 0.f;
        #pragma unroll
        for (int s = 0; s < SS; s++) { ex[s] = fexp(lg[s] - mx); tot += ex[s]; }
        float inv = __fdividef(1.f, tot);

        if (half == 0) {
            #pragma unroll
            for (int s = 0; s < SS; s++) {
                float p = fmaf(ex[s], inv, EPSV);
                prsw[tl*8 + s] = p * r;
            }
            prsw[tl*8 + 7] = inv_r;
            prsw[128 + tl] = m;
        }
    }
    __syncwarp();

    // den / c2 (lanes 0..13): p = pr*inv_r, c2 term = pr*m
    if (lane < 14) {
        int s7 = (lane < 7) ? lane : lane - 7;
        float val = 0.f;
        if (lane < 7) {
            #pragma unroll
            for (int t = 0; t < 16; t++) val += prsw[t*8 + s7] * prsw[t*8 + 7];
            atomicAdd(&g_den[b*SS + s7], val);
        } else {
            #pragma unroll
            for (int t = 0; t < 16; t++) val += prsw[t*8 + s7] * prsw[128 + t];
            atomicAdd(&g_c2[b*SS + s7], val);
        }
    }

    // phase B: warp-local outer product over its 16 tokens
    {
        int h = lane >> 4, e4 = lane & 15;
        u64 acca[SS], accb[SS];
        #pragma unroll
        for (int s = 0; s < SS; s++) { acca[s] = 0; accb[s] = 0; }
        #pragma unroll
        for (int j = 0; j < 8; j++) {
            int t = 2*j + h;
            ulonglong2 xv = *(const ulonglong2*)(xsw + t*17 + e4);
            float4 p0 = *(const float4*)(prsw + t*8);
            float4 p1 = *(const float4*)(prsw + t*8 + 4);
            u64 q0 = pk(p0.x, p0.x), q1 = pk(p0.y, p0.y);
            u64 q2 = pk(p0.z, p0.z), q3 = pk(p0.w, p0.w);
            u64 q4 = pk(p1.x, p1.x), q5 = pk(p1.y, p1.y);
            u64 q6 = pk(p1.z, p1.z);
            fma2(acca[0], xv.x, q0); fma2(accb[0], xv.y, q0);
            fma2(acca[1], xv.x, q1); fma2(accb[1], xv.y, q1);
            fma2(acca[2], xv.x, q2); fma2(accb[2], xv.y, q2);
            fma2(acca[3], xv.x, q3); fma2(accb[3], xv.y, q3);
            fma2(acca[4], xv.x, q4); fma2(accb[4], xv.y, q4);
            fma2(acca[5], xv.x, q5); fma2(accb[5], xv.y, q5);
            fma2(acca[6], xv.x, q6); fma2(accb[6], xv.y, q6);
        }
        float4* psumw = xsw;   // reuse own xs region
        #pragma unroll
        for (int s = 0; s < SS; s++) {
            u64 oa = __shfl_xor_sync(0xffffffffu, acca[s], 16);
            u64 ob = __shfl_xor_sync(0xffffffffu, accb[s], 16);
            add2(acca[s], oa); add2(accb[s], ob);
            if (h == 0) {
                float4 o;
                upk(acca[s], o.x, o.y);
                upk(accb[s], o.z, o.w);
                psumw[s*16 + e4] = o;
            }
        }
    }
    __syncthreads();

    if (tid < 112) {
        int s = tid >> 4, e4 = tid & 15;
        float4 acc = make_float4(0.f, 0.f, 0.f, 0.f);
        #pragma unroll
        for (int w2 = 0; w2 < 8; w2++) {
            float4 v = ((const float4*)(smf + AT_XS))[w2*272 + s*16 + e4];
            acc.x += v.x; acc.y += v.y; acc.z += v.z; acc.w += v.w;
        }
        float* up = g_u + (b*SS + s)*DD + e4*4;
        atomicAdd(up+0, acc.x); atomicAdd(up+1, acc.y);
        atomicAdd(up+2, acc.z); atomicAdd(up+3, acc.w);
    }
}

// ---------------------------------------------------------------------------
// finalize: one block per (batch, slot) = 896 blocks, 192 threads.
// PDL: prefetch weights (L1/L2 warm) -> wait -> compute.
// `early`: issue launch_dependents at start (0 for iter0 to protect g_xh).
__global__ void __launch_bounds__(192) k_finalize(
        const float* __restrict__ b_ih, const float* __restrict__ b_hh,
        const float* __restrict__ b1,  const float* __restrict__ b2,
        const float* __restrict__ ln_mlp_w, const float* __restrict__ ln_mlp_b,
        const float* __restrict__ ln_slots_w, const float* __restrict__ ln_slots_b,
        const float* __restrict__ ln_in_w, const float* __restrict__ ln_in_b,
        float* __restrict__ out, int last, int early) {
    __shared__ float upd[64], prev[64], giv[192], ghv[192],
                     act[64], mln[64], h1[128], red[8];
    int bs = blockIdx.x;
    int tid = threadIdx.x;

    if (early) PDL_TRIGGER();

    // ---- prologue: prefetch weights while predecessor attn drains ----
    {
        float acc = 0.f;
        #pragma unroll 8
        for (int e = 0; e < 64; e++)
            acc += g_CT[e*192 + tid] + g_WHHT[e*192 + tid];
        if (tid < 128) {
            #pragma unroll 8
            for (int e = 0; e < 64; e++) acc += g_W1T[e*128 + tid];
        }
        if (tid < 64) {
            #pragma unroll 8
            for (int j = 0; j < 128; j++) acc += g_W2T[j*64 + tid];
            #pragma unroll 8
            for (int e = 0; e < 64; e++) acc += g_M[e*64 + tid];
        }
        asm volatile("" :: "f"(acc));
    }

    PDL_WAIT();      // g_u/g_den/g_c2/g_slots from predecessor attn

    if (tid < 64) {
        float invden = __fdividef(1.f, g_den[bs]);
        upd[tid] = fmaf(ln_in_w[tid]*invden, g_u[bs*64 + tid] - g_c2[bs],
                        ln_in_b[tid]);
        prev[tid] = g_slots[bs*64 + tid];
    }
    __syncthreads();

    // gi = upd@C^T + b_ih ; gh = prev@W_hh^T + b_hh  (2 accs each)
    {
        float ai0 = b_ih[tid], ah0 = b_hh[tid];
        float ai1 = 0.f, ah1 = 0.f;
        #pragma unroll 16
        for (int e = 0; e < 64; e += 2) {
            ai0 = fmaf(upd[e],    g_CT[e*192 + tid],       ai0);
            ai1 = fmaf(upd[e+1],  g_CT[(e+1)*192 + tid],   ai1);
            ah0 = fmaf(prev[e],   g_WHHT[e*192 + tid],     ah0);
            ah1 = fmaf(prev[e+1], g_WHHT[(e+1)*192 + tid], ah1);
        }
        giv[tid] = ai0 + ai1; ghv[tid] = ah0 + ah1;
    }
    __syncthreads();

    // GRU + LN partials
    if (tid < 64) {
        float r = 1.f/(1.f + __expf(-(giv[tid]     + ghv[tid])));
        float z = 1.f/(1.f + __expf(-(giv[64+tid]  + ghv[64+tid])));
        float n = ftanh(fmaf(r, ghv[128+tid], giv[128+tid]));
        float v = (1.f - z)*n + z*prev[tid];
        act[tid] = v;
        float sum = v, sq = v*v;
        #pragma unroll
        for (int o = 16; o; o >>= 1) {
            sum += __shfl_xor_sync(0xffffffffu, sum, o);
            sq  += __shfl_xor_sync(0xffffffffu, sq,  o);
        }
        if ((tid & 31) == 0) { red[(tid>>5)*2] = sum; red[(tid>>5)*2+1] = sq; }
    }
    __syncthreads();

    if (tid < 64) {
        float sum = red[0] + red[2], sq = red[1] + red[3];
        float m = sum * (1.f/64.f);
        float var = sq * (1.f/64.f) - m*m;
        float r = rsqrtf(var + LN_EPS);
        mln[tid] = (act[tid] - m)*r*ln_mlp_w[tid] + ln_mlp_b[tid];
    }
    __syncthreads();

    if (tid < 128) {
        float a0 = b1[tid], a1 = 0.f;
        #pragma unroll 16
        for (int e = 0; e < 64; e += 2) {
            a0 = fmaf(mln[e],   g_W1T[e*128 + tid],     a0);
            a1 = fmaf(mln[e+1], g_W1T[(e+1)*128 + tid], a1);
        }
        h1[tid] = fmaxf(a0 + a1, 0.f);
    }
    __syncthreads();

    float res = 0.f;
    if (tid < 64) {
        float a0 = b2[tid], a1 = 0.f, a2 = 0.f, a3 = 0.f;
        #pragma unroll 8
        for (int j = 0; j < 128; j += 4) {
            a0 = fmaf(h1[j],   g_W2T[j*64 + tid],     a0);
            a1 = fmaf(h1[j+1], g_W2T[(j+1)*64 + tid], a1);
            a2 = fmaf(h1[j+2], g_W2T[(j+2)*64 + tid], a2);
            a3 = fmaf(h1[j+3], g_W2T[(j+3)*64 + tid], a3);
        }
        res = act[tid] + (a0 + a1) + (a2 + a3);
        g_slots[bs*64 + tid] = res;
        if (last) out[bs*64 + tid] = res;
    }
    if (last) return;
    __syncthreads();

    // next-iteration prep: LN(res) -> qt -> qw/sw/sb ; zero accumulators
    if (tid < 64) {
        float sum = res, sq = res*res;
        #pragma unroll
        for (int o = 16; o; o >>= 1) {
            sum += __shfl_xor_sync(0xffffffffu, sum, o);
            sq  += __shfl_xor_sync(0xffffffffu, sq,  o);
        }
        if ((tid & 31) == 0) { red[(tid>>5)*2] = sum; red[(tid>>5)*2+1] = sq; }
        g_u[bs*64 + tid] = 0.f;
    }
    if (tid == 0) { g_den[bs] = 0.f; g_c2[bs] = 0.f; }
    __syncthreads();

    if (tid < 64) {
        float sum = red[0] + red[2], sq = red[1] + red[3];
        float m = sum * (1.f/64.f);
        float var = sq * (1.f/64.f) - m*m;
        float r = rsqrtf(var + LN_EPS);
        mln[tid] = (res - m)*r*ln_slots_w[tid] + ln_slots_b[tid];   // reuse as sn
    }
    __syncthreads();

    if (tid < 64) {
        float a0 = 0.f, a1 = 0.f;
        #pragma unroll 16
        for (int e = 0; e < 64; e += 2) {
            a0 = fmaf(mln[e],   g_M[e*64 + tid],     a0);
            a1 = fmaf(mln[e+1], g_M[(e+1)*64 + tid], a1);
        }
        float acc = a0 + a1;
        g_qt[bs*64 + tid] = acc * ln_in_w[tid];
        float pa = acc * ln_in_w[tid];
        float pb = acc * ln_in_b[tid];
        #pragma unroll
        for (int o = 16; o; o >>= 1) {
            pa += __shfl_xor_sync(0xffffffffu, pa, o);
            pb += __shfl_xor_sync(0xffffffffu, pb, o);
        }
        if ((tid & 31) == 0) { red[(tid>>5)*2] = pa; red[(tid>>5)*2+1] = pb; }
    }
    __syncthreads();
    if (tid == 0) {
        g_qsc[bs*2 + 0] = red[0] + red[2];
        g_qsc[bs*2 + 1] = red[1] + red[3];
    }
}

// ---------------------------------------------------------------------------
extern "C" void kernel_launch(void* const* d_in, const int* in_sizes, int n_in,
                              void* d_out, int out_size) {
    const float* inputs     = (const float*)d_in[0];
    const float* noise      = (const float*)d_in[1];
    const float* ln_in_w    = (const float*)d_in[2];
    const float* ln_in_b    = (const float*)d_in[3];
    const float* ln_slots_w = (const float*)d_in[4];
    const float* ln_slots_b = (const float*)d_in[5];
    const float* ln_mlp_w   = (const float*)d_in[6];
    const float* ln_mlp_b   = (const float*)d_in[7];
    const float* mu         = (const float*)d_in[8];
    const float* logsig     = (const float*)d_in[9];
    const float* Wq         = (const float*)d_in[10];
    const float* Wk         = (const float*)d_in[11];
    const float* Wv         = (const float*)d_in[12];
    const float* W_ih       = (const float*)d_in[13];
    const float* W_hh       = (const float*)d_in[14];
    const float* b_ih       = (const float*)d_in[15];
    const float* b_hh       = (const float*)d_in[16];
    const float* W1         = (const float*)d_in[17];
    const float* b1         = (const float*)d_in[18];
    const float* W2         = (const float*)d_in[19];
    const float* b2         = (const float*)d_in[20];
    float* out = (float*)d_out;

    cudaFuncSetAttribute(k_attn<1>, cudaFuncAttributeMaxDynamicSharedMemorySize,
                         AT_TOT*4);
    cudaFuncSetAttribute(k_attn<0>, cudaFuncAttributeMaxDynamicSharedMemorySize,
                         AT_TOT*4);

    cudaLaunchAttribute pdlAttr[1];
    pdlAttr[0].id = cudaLaunchAttributeProgrammaticStreamSerialization;
    pdlAttr[0].val.programmaticStreamSerializationAllowed = 1;

    // precomp: plain launch (first in chain)
    k_precomp<<<176, 256>>>(Wq, Wk, W_ih, Wv, W_hh, W1, W2);

    {   // q0 as PDL secondary of precomp
        cudaLaunchConfig_t cfg = {};
        cfg.gridDim = dim3(BB); cfg.blockDim = dim3(256);
        cfg.attrs = pdlAttr; cfg.numAttrs = 1;
        cudaLaunchKernelEx(&cfg, k_q0, noise, mu, logsig,
                           ln_slots_w, ln_slots_b, ln_in_w, ln_in_b);
    }

    dim3 grid(NN/128, BB);
    for (int it = 0; it < NUM_ITERS; it++) {
        {
            cudaLaunchConfig_t cfg = {};
            cfg.gridDim = grid; cfg.blockDim = dim3(256);
            cfg.dynamicSmemBytes = AT_TOT*4;
            cfg.attrs = pdlAttr; cfg.numAttrs = 1;
            if (it == 0) cudaLaunchKernelEx(&cfg, k_attn<1>, inputs);
            else         cudaLaunchKernelEx(&cfg, k_attn<0>, inputs);
        }
        {
            cudaLaunchConfig_t cfg = {};
            cfg.gridDim = dim3(BB*SS); cfg.blockDim = dim3(192);
            cfg.attrs = pdlAttr; cfg.numAttrs = 1;
            int last  = (it == NUM_ITERS - 1) ? 1 : 0;
            int early = (it == 0) ? 0 : 1;   // protect attn1's g_xh staging vs attn0
            cudaLaunchKernelEx(&cfg, k_finalize, b_ih, b_hh, b1, b2,
                               ln_mlp_w, ln_mlp_b, ln_slots_w, ln_slots_b,
                               ln_in_w, ln_in_b, out, last, early);
        }
    }
}